// round 6
// baseline (speedup 1.0000x reference)
#include <cuda_runtime.h>
#include <cuda_bf16.h>
#include <math.h>
#include <stdint.h>

#define N_TOK 4096
#define CDIM 256
#define HEADS 16
#define DHEAD 64
#define HD 1024
#define NQ 64
#define NKEY 256
#define NTRUNK 64
#define PADL 96

extern __shared__ char dyn_smem[];

// ---------------- scratch (device globals) ----------------
__device__ float g_gate[N_TOK * HD];
__device__ float g_o[N_TOK * HD];

__device__ __align__(16) __nv_bfloat16 g_aq_hi[N_TOK * CDIM];
__device__ __align__(16) __nv_bfloat16 g_aq_lo[N_TOK * CDIM];
__device__ __align__(16) __nv_bfloat16 g_akv_hi[N_TOK * CDIM];
__device__ __align__(16) __nv_bfloat16 g_akv_lo[N_TOK * CDIM];
__device__ __align__(16) __nv_bfloat16 g_wt_hi[4 * HD * CDIM];   // [mat][n][k]
__device__ __align__(16) __nv_bfloat16 g_wt_lo[4 * HD * CDIM];
__device__ __align__(16) __nv_bfloat16 g_wot_hi[CDIM * HD];      // [n][k]
__device__ __align__(16) __nv_bfloat16 g_wot_lo[CDIM * HD];
__device__ __align__(16) __nv_bfloat16 g_og_hi[N_TOK * HD];
__device__ __align__(16) __nv_bfloat16 g_og_lo[N_TOK * HD];

// attention operands (bf16 hi/lo), q pre-scaled by 1/8
__device__ __align__(16) __nv_bfloat16 g_qh[HEADS * N_TOK * DHEAD];  // [h][n][d]
__device__ __align__(16) __nv_bfloat16 g_ql[HEADS * N_TOK * DHEAD];
__device__ __align__(16) __nv_bfloat16 g_kh[HEADS * N_TOK * DHEAD];  // [h][n][d]
__device__ __align__(16) __nv_bfloat16 g_kl[HEADS * N_TOK * DHEAD];
__device__ __align__(16) __nv_bfloat16 g_vth[HEADS * DHEAD * N_TOK]; // [h][d][n]
__device__ __align__(16) __nv_bfloat16 g_vtl[HEADS * DHEAD * N_TOK];

// ---------------- helpers (base PTX ISA) -------
__device__ __forceinline__ uint32_t smem_u32(const void* p) {
    uint32_t a;
    asm("{ .reg .u64 t; cvta.to.shared.u64 t, %1; cvt.u32.u64 %0, t; }" : "=r"(a) : "l"(p));
    return a;
}

__device__ __forceinline__ void ldm_x4(uint32_t addr, uint32_t* r) {
    asm volatile("ldmatrix.sync.aligned.m8n8.x4.shared.b16 {%0,%1,%2,%3}, [%4];"
                 : "=r"(r[0]), "=r"(r[1]), "=r"(r[2]), "=r"(r[3]) : "r"(addr));
}

__device__ __forceinline__ void mma16816(float* c, const uint32_t* a, uint32_t b0, uint32_t b1) {
    asm volatile(
        "mma.sync.aligned.m16n8k16.row.col.f32.bf16.bf16.f32 "
        "{%0,%1,%2,%3}, {%4,%5,%6,%7}, {%8,%9}, {%0,%1,%2,%3};"
        : "+f"(c[0]), "+f"(c[1]), "+f"(c[2]), "+f"(c[3])
        : "r"(a[0]), "r"(a[1]), "r"(a[2]), "r"(a[3]), "r"(b0), "r"(b1));
}

__device__ __forceinline__ uint32_t pack_bf16x2(float x0, float x1) {
    __nv_bfloat162 p;
    p.x = __float2bfloat16(x0);
    p.y = __float2bfloat16(x1);
    return *(uint32_t*)&p;
}

__device__ __forceinline__ void cp16(uint32_t d, const void* s) {
    asm volatile("cp.async.cg.shared.global [%0], [%1], 16;" :: "r"(d), "l"(s));
}

// ---------------------------------------------------------------------------
// pipelined dense GEMM core (CTA 128x128, BK=32, 8 warps 64x32, bf16x3,
// cp.async 2-stage double buffer in dynamic smem: 2 x 40960 B)
// ---------------------------------------------------------------------------
#define SPITCH 40
#define STAGE_BYTES 40960
#define A_HI 0
#define A_LO 10240
#define B_HI 20480
#define B_LO 30720
#define SMEM_GEMM (2 * STAGE_BYTES)

__device__ __forceinline__ void gemm_pipe(
    const __nv_bfloat16* __restrict__ Ah, const __nv_bfloat16* __restrict__ Al,
    const __nv_bfloat16* __restrict__ Bh, const __nv_bfloat16* __restrict__ Bl,
    int K, float acc[4][4][4])
{
    const int tid = threadIdx.x, lane = tid & 31, warp = tid >> 5;
    const int wm = warp >> 2, wn = warp & 3;
    const int lrow = lane & 15, lcolh = (lane >> 4) * 8;
    const uint32_t sbase = smem_u32(dyn_smem);

    const int r0 = tid >> 2, g0 = (tid & 3) * 8;          // elements
    const int r1 = (tid + 256) >> 2, g1 = ((tid + 256) & 3) * 8;
    const uint32_t ds0 = (uint32_t)(r0 * SPITCH + g0) * 2;
    const uint32_t ds1 = (uint32_t)(r1 * SPITCH + g1) * 2;

    // prologue: stage 0
    {
        size_t o0 = (size_t)r0 * K + g0;
        size_t o1 = (size_t)r1 * K + g1;
        uint32_t d0 = sbase + ds0, d1 = sbase + ds1;
        cp16(d0 + A_HI, Ah + o0); cp16(d1 + A_HI, Ah + o1);
        cp16(d0 + A_LO, Al + o0); cp16(d1 + A_LO, Al + o1);
        cp16(d0 + B_HI, Bh + o0); cp16(d1 + B_HI, Bh + o1);
        cp16(d0 + B_LO, Bl + o0); cp16(d1 + B_LO, Bl + o1);
        asm volatile("cp.async.commit_group;");
    }

    const int nk = K >> 5;
    for (int kc = 0; kc < nk; kc++) {
        asm volatile("cp.async.wait_group 0;");
        __syncthreads();
        if (kc + 1 < nk) {
            int kb = (kc + 1) << 5;
            uint32_t st = sbase + ((kc + 1) & 1) * STAGE_BYTES;
            size_t o0 = (size_t)r0 * K + kb + g0;
            size_t o1 = (size_t)r1 * K + kb + g1;
            uint32_t d0 = st + ds0, d1 = st + ds1;
            cp16(d0 + A_HI, Ah + o0); cp16(d1 + A_HI, Ah + o1);
            cp16(d0 + A_LO, Al + o0); cp16(d1 + A_LO, Al + o1);
            cp16(d0 + B_HI, Bh + o0); cp16(d1 + B_HI, Bh + o1);
            cp16(d0 + B_LO, Bl + o0); cp16(d1 + B_LO, Bl + o1);
            asm volatile("cp.async.commit_group;");
        }
        uint32_t sb = sbase + (kc & 1) * STAGE_BYTES;
        #pragma unroll
        for (int ks = 0; ks < 2; ks++) {
            uint32_t ah[4][4], al[4][4];
            #pragma unroll
            for (int mt = 0; mt < 4; mt++) {
                uint32_t ro = (uint32_t)((wm * 64 + mt * 16 + lrow) * SPITCH + ks * 16 + lcolh) * 2;
                ldm_x4(sb + A_HI + ro, ah[mt]);
                ldm_x4(sb + A_LO + ro, al[mt]);
            }
            #pragma unroll
            for (int bt = 0; bt < 2; bt++) {
                uint32_t bh[4], bl[4];
                uint32_t ro = (uint32_t)((wn * 32 + bt * 16 + lrow) * SPITCH + ks * 16 + lcolh) * 2;
                ldm_x4(sb + B_HI + ro, bh);
                ldm_x4(sb + B_LO + ro, bl);
                #pragma unroll
                for (int mt = 0; mt < 4; mt++) {
                    mma16816(acc[mt][bt * 2],     ah[mt], bh[0], bh[2]);
                    mma16816(acc[mt][bt * 2],     al[mt], bh[0], bh[2]);
                    mma16816(acc[mt][bt * 2],     ah[mt], bl[0], bl[2]);
                    mma16816(acc[mt][bt * 2 + 1], ah[mt], bh[1], bh[3]);
                    mma16816(acc[mt][bt * 2 + 1], al[mt], bh[1], bh[3]);
                    mma16816(acc[mt][bt * 2 + 1], ah[mt], bl[1], bl[3]);
                }
            }
        }
        __syncthreads();
    }
}

// ---------------------------------------------------------------------------
// conversions
// ---------------------------------------------------------------------------
__global__ __launch_bounds__(256) void conv_act(const float* __restrict__ qx,
                                                const float* __restrict__ kvx)
{
    int idx = blockIdx.x * 256 + threadIdx.x;
    const float* src = blockIdx.y ? kvx : qx;
    __nv_bfloat16* hi = blockIdx.y ? g_akv_hi : g_aq_hi;
    __nv_bfloat16* lo = blockIdx.y ? g_akv_lo : g_aq_lo;
    float x = src[idx];
    __nv_bfloat16 h = __float2bfloat16(x);
    hi[idx] = h;
    lo[idx] = __float2bfloat16(x - __bfloat162float(h));
}

__global__ __launch_bounds__(256) void conv_w(
    const float* __restrict__ Wq, const float* __restrict__ Wk,
    const float* __restrict__ Wv, const float* __restrict__ Wg,
    const float* __restrict__ Wo)
{
    int z = blockIdx.z;
    const float* in; int R, C; __nv_bfloat16 *oh, *ol;
    if (z < 4) {
        in = (z == 0) ? Wq : (z == 1) ? Wk : (z == 2) ? Wv : Wg;
        R = CDIM; C = HD; oh = g_wt_hi + (size_t)z * HD * CDIM; ol = g_wt_lo + (size_t)z * HD * CDIM;
    } else {
        in = Wo; R = HD; C = CDIM; oh = g_wot_hi; ol = g_wot_lo;
    }
    int c0 = blockIdx.x * 32, r0 = blockIdx.y * 32;
    if (c0 >= C || r0 >= R) return;
    __shared__ float t[32][33];
    int tx = threadIdx.x & 31, ty = threadIdx.x >> 5;
    for (int i = ty; i < 32; i += 8) t[i][tx] = in[(size_t)(r0 + i) * C + c0 + tx];
    __syncthreads();
    for (int i = ty; i < 32; i += 8) {
        float x = t[tx][i];
        __nv_bfloat16 h = __float2bfloat16(x);
        size_t o = (size_t)(c0 + i) * R + r0 + tx;
        oh[o] = h;
        ol[o] = __float2bfloat16(x - __bfloat162float(h));
    }
}

__global__ __launch_bounds__(256) void conv_og()
{
    int idx = blockIdx.x * 256 + threadIdx.x;
    float x = g_o[idx] * g_gate[idx];
    __nv_bfloat16 h = __float2bfloat16(x);
    g_og_hi[idx] = h;
    g_og_lo[idx] = __float2bfloat16(x - __bfloat162float(h));
}

// ---------------------------------------------------------------------------
// projection GEMMs: grid (HD/128=8, N_TOK/128=32, 4 mats)
// ---------------------------------------------------------------------------
__global__ __launch_bounds__(256, 2) void mm_proj_tc()
{
    const int mat = blockIdx.z;
    const int m0 = blockIdx.y * 128, n0 = blockIdx.x * 128;
    const __nv_bfloat16* Ah = ((mat == 1 || mat == 2) ? g_akv_hi : g_aq_hi) + (size_t)m0 * CDIM;
    const __nv_bfloat16* Al = ((mat == 1 || mat == 2) ? g_akv_lo : g_aq_lo) + (size_t)m0 * CDIM;
    const __nv_bfloat16* Bh = g_wt_hi + (size_t)mat * HD * CDIM + (size_t)n0 * CDIM;
    const __nv_bfloat16* Bl = g_wt_lo + (size_t)mat * HD * CDIM + (size_t)n0 * CDIM;

    float acc[4][4][4] = {};
    gemm_pipe(Ah, Al, Bh, Bl, CDIM, acc);

    const int lane = threadIdx.x & 31, warp = threadIdx.x >> 5;
    const int wm = warp >> 2, wn = warp & 3;
    #pragma unroll
    for (int mt = 0; mt < 4; mt++) {
        #pragma unroll
        for (int nt = 0; nt < 4; nt++) {
            #pragma unroll
            for (int rr = 0; rr < 2; rr++) {
                int m = m0 + wm * 64 + mt * 16 + (lane >> 2) + rr * 8;
                int c = n0 + wn * 32 + nt * 8 + (lane & 3) * 2;
                float v0 = acc[mt][nt][rr * 2], v1 = acc[mt][nt][rr * 2 + 1];
                int hh = c >> 6, d = c & 63;
                if (mat == 0) {
                    float x0 = v0 * 0.125f, x1 = v1 * 0.125f;
                    __nv_bfloat16 b0 = __float2bfloat16(x0), b1 = __float2bfloat16(x1);
                    __nv_bfloat162 ph; ph.x = b0; ph.y = b1;
                    __nv_bfloat162 pl;
                    pl.x = __float2bfloat16(x0 - __bfloat162float(b0));
                    pl.y = __float2bfloat16(x1 - __bfloat162float(b1));
                    size_t o = ((size_t)hh * N_TOK + m) * DHEAD + d;
                    *(__nv_bfloat162*)&g_qh[o] = ph;
                    *(__nv_bfloat162*)&g_ql[o] = pl;
                } else if (mat == 1) {
                    __nv_bfloat16 b0 = __float2bfloat16(v0), b1 = __float2bfloat16(v1);
                    __nv_bfloat162 ph; ph.x = b0; ph.y = b1;
                    __nv_bfloat162 pl;
                    pl.x = __float2bfloat16(v0 - __bfloat162float(b0));
                    pl.y = __float2bfloat16(v1 - __bfloat162float(b1));
                    size_t o = ((size_t)hh * N_TOK + m) * DHEAD + d;
                    *(__nv_bfloat162*)&g_kh[o] = ph;
                    *(__nv_bfloat162*)&g_kl[o] = pl;
                } else if (mat == 2) {
                    __nv_bfloat16 b0 = __float2bfloat16(v0), b1 = __float2bfloat16(v1);
                    size_t o0 = ((size_t)hh * DHEAD + d) * N_TOK + m;
                    size_t o1 = ((size_t)hh * DHEAD + d + 1) * N_TOK + m;
                    g_vth[o0] = b0;
                    g_vth[o1] = b1;
                    g_vtl[o0] = __float2bfloat16(v0 - __bfloat162float(b0));
                    g_vtl[o1] = __float2bfloat16(v1 - __bfloat162float(b1));
                } else {
                    float2 v = make_float2(1.f / (1.f + expf(-v0)), 1.f / (1.f + expf(-v1)));
                    *(float2*)&g_gate[(size_t)m * HD + c] = v;
                }
            }
        }
    }
}

// output GEMM
__global__ __launch_bounds__(256, 2) void mm_out_tc(float* __restrict__ out)
{
    const int m0 = blockIdx.y * 128, n0 = blockIdx.x * 128;
    float acc[4][4][4] = {};
    gemm_pipe(g_og_hi + (size_t)m0 * HD, g_og_lo + (size_t)m0 * HD,
              g_wot_hi + (size_t)n0 * HD, g_wot_lo + (size_t)n0 * HD, HD, acc);

    const int lane = threadIdx.x & 31, warp = threadIdx.x >> 5;
    const int wm = warp >> 2, wn = warp & 3;
    #pragma unroll
    for (int mt = 0; mt < 4; mt++) {
        #pragma unroll
        for (int nt = 0; nt < 4; nt++) {
            #pragma unroll
            for (int rr = 0; rr < 2; rr++) {
                int m = m0 + wm * 64 + mt * 16 + (lane >> 2) + rr * 8;
                int c = n0 + wn * 32 + nt * 8 + (lane & 3) * 2;
                *(float2*)&out[(size_t)m * CDIM + c] =
                    make_float2(acc[mt][nt][rr * 2], acc[mt][nt][rr * 2 + 1]);
            }
        }
    }
}

// ---------------------------------------------------------------------------
// tensor-core local attention (unchanged from round 5)
// ---------------------------------------------------------------------------
#define QP 72
#define VP 264

__global__ __launch_bounds__(256) void attn_tc(const float* __restrict__ bias)
{
    __nv_bfloat16* Sb = (__nv_bfloat16*)dyn_smem;
    __nv_bfloat16* sQh = Sb;
    __nv_bfloat16* sQl = Sb + 4608;
    __nv_bfloat16* sKh = Sb + 9216;
    __nv_bfloat16* sKl = Sb + 27648;
    __nv_bfloat16* sVh = Sb + 9216;
    __nv_bfloat16* sVl = Sb + 26112;
    float* sO = (float*)dyn_smem;
    float* pm = (float*)(dyn_smem + 92160);
    float* ps = (float*)(dyn_smem + 92672);

    const int h = blockIdx.x, t = blockIdx.y;
    const int tid = threadIdx.x, lane = tid & 31, warp = tid >> 5;
    const int wm = warp & 3, ch = warp >> 2;
    const int kbase = t * NQ - PADL;
    const int lrow = lane & 15, lcolh = (lane >> 4) * 8;
    const int l4 = lane >> 2, lq = lane & 3;

    {
        const __nv_bfloat16* qh = g_qh + ((size_t)h * N_TOK + t * NQ) * DHEAD;
        const __nv_bfloat16* ql = g_ql + ((size_t)h * N_TOK + t * NQ) * DHEAD;
        #pragma unroll
        for (int i = 0; i < 2; i++) {
            int idx = tid + i * 256;
            int r = idx >> 3, g = idx & 7;
            *(uint4*)&sQh[r * QP + g * 8] = *(const uint4*)&qh[idx * 8];
            *(uint4*)&sQl[r * QP + g * 8] = *(const uint4*)&ql[idx * 8];
        }
        #pragma unroll
        for (int i = 0; i < 8; i++) {
            int idx = tid + i * 256;
            int r = idx >> 3, g = idx & 7;
            int gk = kbase + r;
            uint4 vh = {0, 0, 0, 0}, vl = {0, 0, 0, 0};
            if (gk >= 0 && gk < N_TOK) {
                size_t src = ((size_t)h * N_TOK + gk) * DHEAD + g * 8;
                vh = *(const uint4*)&g_kh[src];
                vl = *(const uint4*)&g_kl[src];
            }
            *(uint4*)&sKh[r * QP + g * 8] = vh;
            *(uint4*)&sKl[r * QP + g * 8] = vl;
        }
    }
    __syncthreads();

    uint32_t ah[4][4], al[4][4];
    #pragma unroll
    for (int kc = 0; kc < 4; kc++) {
        int ro = (wm * 16 + lrow) * QP + kc * 16 + lcolh;
        ldm_x4(smem_u32(&sQh[ro]), ah[kc]);
        ldm_x4(smem_u32(&sQl[ro]), al[kc]);
    }
    float acc[16][4];
    #pragma unroll
    for (int i = 0; i < 16; i++) { acc[i][0] = 0.f; acc[i][1] = 0.f; acc[i][2] = 0.f; acc[i][3] = 0.f; }
    #pragma unroll
    for (int nt = 0; nt < 8; nt++) {
        #pragma unroll
        for (int kc = 0; kc < 4; kc++) {
            uint32_t bh[4], bl[4];
            int ro = (ch * 128 + nt * 16 + lrow) * QP + kc * 16 + lcolh;
            ldm_x4(smem_u32(&sKh[ro]), bh);
            ldm_x4(smem_u32(&sKl[ro]), bl);
            mma16816(acc[2 * nt],     ah[kc], bh[0], bh[2]);
            mma16816(acc[2 * nt],     al[kc], bh[0], bh[2]);
            mma16816(acc[2 * nt],     ah[kc], bl[0], bl[2]);
            mma16816(acc[2 * nt + 1], ah[kc], bh[1], bh[3]);
            mma16816(acc[2 * nt + 1], al[kc], bh[1], bh[3]);
            mma16816(acc[2 * nt + 1], ah[kc], bl[1], bl[3]);
        }
    }

    {
        const int r0 = t * NQ + wm * 16 + l4;
        const int c0 = kbase + ch * 128 + lq * 2;
        #pragma unroll
        for (int nt = 0; nt < 16; nt++) {
            int gc = c0 + nt * 8;
            if (gc >= 0 && gc < N_TOK) {
                float2 b0 = *(const float2*)&bias[(size_t)r0 * N_TOK + gc];
                float2 b1 = *(const float2*)&bias[(size_t)(r0 + 8) * N_TOK + gc];
                acc[nt][0] += b0.x; acc[nt][1] += b0.y;
                acc[nt][2] += b1.x; acc[nt][3] += b1.y;
            }
        }
    }

    const int rloc = wm * 16 + l4;
    float mx0 = -1e30f, mx1 = -1e30f;
    #pragma unroll
    for (int nt = 0; nt < 16; nt++) {
        mx0 = fmaxf(mx0, fmaxf(acc[nt][0], acc[nt][1]));
        mx1 = fmaxf(mx1, fmaxf(acc[nt][2], acc[nt][3]));
    }
    mx0 = fmaxf(mx0, __shfl_xor_sync(0xffffffffu, mx0, 1));
    mx0 = fmaxf(mx0, __shfl_xor_sync(0xffffffffu, mx0, 2));
    mx1 = fmaxf(mx1, __shfl_xor_sync(0xffffffffu, mx1, 1));
    mx1 = fmaxf(mx1, __shfl_xor_sync(0xffffffffu, mx1, 2));
    if (lq == 0) { pm[ch * 64 + rloc] = mx0; pm[ch * 64 + rloc + 8] = mx1; }
    __syncthreads();

    float M0 = fmaxf(pm[rloc], pm[64 + rloc]);
    float M1 = fmaxf(pm[rloc + 8], pm[64 + rloc + 8]);
    float s0 = 0.f, s1 = 0.f;
    #pragma unroll
    for (int nt = 0; nt < 16; nt++) {
        acc[nt][0] = __expf(acc[nt][0] - M0); s0 += acc[nt][0];
        acc[nt][1] = __expf(acc[nt][1] - M0); s0 += acc[nt][1];
        acc[nt][2] = __expf(acc[nt][2] - M1); s1 += acc[nt][2];
        acc[nt][3] = __expf(acc[nt][3] - M1); s1 += acc[nt][3];
    }
    s0 += __shfl_xor_sync(0xffffffffu, s0, 1);
    s0 += __shfl_xor_sync(0xffffffffu, s0, 2);
    s1 += __shfl_xor_sync(0xffffffffu, s1, 1);
    s1 += __shfl_xor_sync(0xffffffffu, s1, 2);
    if (lq == 0) { ps[ch * 64 + rloc] = s0; ps[ch * 64 + rloc + 8] = s1; }

    #pragma unroll
    for (int i = 0; i < 8; i++) {
        int idx = tid + i * 256;
        int d = idx >> 5, g = idx & 31;
        int gk0 = kbase + g * 8;
        uint4 vh = {0, 0, 0, 0}, vl = {0, 0, 0, 0};
        if (gk0 >= 0 && gk0 < N_TOK) {
            size_t src = ((size_t)h * DHEAD + d) * N_TOK + gk0;
            vh = *(const uint4*)&g_vth[src];
            vl = *(const uint4*)&g_vtl[src];
        }
        *(uint4*)&sVh[d * VP + g * 8] = vh;
        *(uint4*)&sVl[d * VP + g * 8] = vl;
    }
    __syncthreads();

    float inv0 = 1.f / (ps[rloc] + ps[64 + rloc]);
    float inv1 = 1.f / (ps[rloc + 8] + ps[64 + rloc + 8]);
    #pragma unroll
    for (int nt = 0; nt < 16; nt++) {
        acc[nt][0] *= inv0; acc[nt][1] *= inv0;
        acc[nt][2] *= inv1; acc[nt][3] *= inv1;
    }

    float oacc[8][4];
    #pragma unroll
    for (int i = 0; i < 8; i++) { oacc[i][0] = 0.f; oacc[i][1] = 0.f; oacc[i][2] = 0.f; oacc[i][3] = 0.f; }
    #pragma unroll
    for (int kc = 0; kc < 8; kc++) {
        uint32_t awh[4], awl[4];
        #pragma unroll
        for (int f = 0; f < 4; f++) {
            int nt = 2 * kc + (f >> 1);
            int j = (f & 1) * 2;
            float x0 = acc[nt][j], x1 = acc[nt][j + 1];
            __nv_bfloat16 b0 = __float2bfloat16(x0), b1 = __float2bfloat16(x1);
            __nv_bfloat162 ph; ph.x = b0; ph.y = b1;
            awh[f] = *(uint32_t*)&ph;
            awl[f] = pack_bf16x2(x0 - __bfloat162float(b0), x1 - __bfloat162float(b1));
        }
        #pragma unroll
        for (int dg = 0; dg < 4; dg++) {
            uint32_t bh[4], bl[4];
            int ro = (dg * 16 + lrow) * VP + ch * 128 + kc * 16 + lcolh;
            ldm_x4(smem_u32(&sVh[ro]), bh);
            ldm_x4(smem_u32(&sVl[ro]), bl);
            mma16816(oacc[2 * dg],     awh, bh[0], bh[2]);
            mma16816(oacc[2 * dg],     awl, bh[0], bh[2]);
            mma16816(oacc[2 * dg],     awh, bl[0], bl[2]);
            mma16816(oacc[2 * dg + 1], awh, bh[1], bh[3]);
            mma16816(oacc[2 * dg + 1], awl, bh[1], bh[3]);
            mma16816(oacc[2 * dg + 1], awh, bl[1], bl[3]);
        }
    }

    __syncthreads();
    if (ch == 1) {
        #pragma unroll
        for (int nt = 0; nt < 8; nt++) {
            int c = nt * 8 + lq * 2;
            sO[(wm * 16 + l4) * 66 + c] = oacc[nt][0];
            sO[(wm * 16 + l4) * 66 + c + 1] = oacc[nt][1];
            sO[(wm * 16 + l4 + 8) * 66 + c] = oacc[nt][2];
            sO[(wm * 16 + l4 + 8) * 66 + c + 1] = oacc[nt][3];
        }
    }
    __syncthreads();
    if (ch == 0) {
        #pragma unroll
        for (int nt = 0; nt < 8; nt++) {
            int r = wm * 16 + l4, c = nt * 8 + lq * 2;
            float2 v0 = make_float2(oacc[nt][0] + sO[r * 66 + c],
                                    oacc[nt][1] + sO[r * 66 + c + 1]);
            float2 v1 = make_float2(oacc[nt][2] + sO[(r + 8) * 66 + c],
                                    oacc[nt][3] + sO[(r + 8) * 66 + c + 1]);
            *(float2*)&g_o[(size_t)(t * NQ + r) * HD + h * DHEAD + c] = v0;
            *(float2*)&g_o[(size_t)(t * NQ + r + 8) * HD + h * DHEAD + c] = v1;
        }
    }
}

// ---------------------------------------------------------------------------
extern "C" void kernel_launch(void* const* d_in, const int* in_sizes, int n_in,
                              void* d_out, int out_size)
{
    const float* qx   = (const float*)d_in[0];
    const float* kvx  = (const float*)d_in[1];
    const float* bias = (const float*)d_in[2];
    const float* Wq   = (const float*)d_in[3];
    const float* Wk   = (const float*)d_in[4];
    const float* Wv   = (const float*)d_in[5];
    const float* Wg   = (const float*)d_in[6];
    const float* Wo   = (const float*)d_in[7];
    float* out = (float*)d_out;

    static int configured = 0;
    if (!configured) {
        cudaFuncSetAttribute(attn_tc, cudaFuncAttributeMaxDynamicSharedMemorySize, 93184);
        cudaFuncSetAttribute(mm_proj_tc, cudaFuncAttributeMaxDynamicSharedMemorySize, SMEM_GEMM);
        cudaFuncSetAttribute(mm_out_tc, cudaFuncAttributeMaxDynamicSharedMemorySize, SMEM_GEMM);
        configured = 1;
    }

    conv_act<<<dim3(N_TOK * CDIM / 256, 2), 256>>>(qx, kvx);
    conv_w<<<dim3(32, 32, 5), 256>>>(Wq, Wk, Wv, Wg, Wo);

    mm_proj_tc<<<dim3(HD / 128, N_TOK / 128, 4), 256, SMEM_GEMM>>>();

    attn_tc<<<dim3(HEADS, NTRUNK), 256, 93184>>>(bias);

    conv_og<<<N_TOK * HD / 256, 256>>>();
    mm_out_tc<<<dim3(CDIM / 128, N_TOK / 128), 256, SMEM_GEMM>>>(out);
}

// round 7
// speedup vs baseline: 1.3456x; 1.3456x over previous
#include <cuda_runtime.h>
#include <cuda_bf16.h>
#include <math.h>
#include <stdint.h>

#define N_TOK 4096
#define CDIM 256
#define HEADS 16
#define DHEAD 64
#define HD 1024
#define NQ 64
#define NKEY 256
#define NTRUNK 64
#define PADL 96

extern __shared__ char dyn_smem[];

// ---------------- scratch (device globals) ----------------
__device__ float g_gate[N_TOK * HD];

__device__ __align__(16) __nv_bfloat16 g_aq_hi[N_TOK * CDIM];
__device__ __align__(16) __nv_bfloat16 g_aq_lo[N_TOK * CDIM];
__device__ __align__(16) __nv_bfloat16 g_akv_hi[N_TOK * CDIM];
__device__ __align__(16) __nv_bfloat16 g_akv_lo[N_TOK * CDIM];
__device__ __align__(16) __nv_bfloat16 g_wt_hi[4 * HD * CDIM];   // [mat][n][k]
__device__ __align__(16) __nv_bfloat16 g_wt_lo[4 * HD * CDIM];
__device__ __align__(16) __nv_bfloat16 g_wot_hi[CDIM * HD];      // [n][k]
__device__ __align__(16) __nv_bfloat16 g_wot_lo[CDIM * HD];
__device__ __align__(16) __nv_bfloat16 g_og_hi[N_TOK * HD];
__device__ __align__(16) __nv_bfloat16 g_og_lo[N_TOK * HD];

// attention operands (bf16 hi/lo), q pre-scaled by 1/8
__device__ __align__(16) __nv_bfloat16 g_qh[HEADS * N_TOK * DHEAD];  // [h][n][d]
__device__ __align__(16) __nv_bfloat16 g_ql[HEADS * N_TOK * DHEAD];
__device__ __align__(16) __nv_bfloat16 g_kh[HEADS * N_TOK * DHEAD];  // [h][n][d]
__device__ __align__(16) __nv_bfloat16 g_kl[HEADS * N_TOK * DHEAD];
__device__ __align__(16) __nv_bfloat16 g_vth[HEADS * DHEAD * N_TOK]; // [h][d][n]
__device__ __align__(16) __nv_bfloat16 g_vtl[HEADS * DHEAD * N_TOK];

// ---------------- warp-mma helpers (base PTX ISA) -------
__device__ __forceinline__ uint32_t smem_u32(const void* p) {
    uint32_t a;
    asm("{ .reg .u64 t; cvta.to.shared.u64 t, %1; cvt.u32.u64 %0, t; }" : "=r"(a) : "l"(p));
    return a;
}

__device__ __forceinline__ void ldm_x4(uint32_t addr, uint32_t* r) {
    asm volatile("ldmatrix.sync.aligned.m8n8.x4.shared.b16 {%0,%1,%2,%3}, [%4];"
                 : "=r"(r[0]), "=r"(r[1]), "=r"(r[2]), "=r"(r[3]) : "r"(addr));
}

__device__ __forceinline__ void mma16816(float* c, const uint32_t* a, uint32_t b0, uint32_t b1) {
    asm volatile(
        "mma.sync.aligned.m16n8k16.row.col.f32.bf16.bf16.f32 "
        "{%0,%1,%2,%3}, {%4,%5,%6,%7}, {%8,%9}, {%0,%1,%2,%3};"
        : "+f"(c[0]), "+f"(c[1]), "+f"(c[2]), "+f"(c[3])
        : "r"(a[0]), "r"(a[1]), "r"(a[2]), "r"(a[3]), "r"(b0), "r"(b1));
}

__device__ __forceinline__ uint32_t pack_bf16x2(float x0, float x1) {
    __nv_bfloat162 p;
    p.x = __float2bfloat16(x0);
    p.y = __float2bfloat16(x1);
    return *(uint32_t*)&p;
}

// ---------------------------------------------------------------------------
// dense GEMM core (CTA 128x128, BK=32, 8 warps 64x32, bf16x3) — R5 version
// ---------------------------------------------------------------------------
#define SPITCH 40

__device__ __forceinline__ void gemm_tc(
    const __nv_bfloat16* __restrict__ Ah, const __nv_bfloat16* __restrict__ Al,
    const __nv_bfloat16* __restrict__ Bh, const __nv_bfloat16* __restrict__ Bl,
    int K, float acc[4][4][4])
{
    __shared__ __align__(16) __nv_bfloat16 sAh[128 * SPITCH];
    __shared__ __align__(16) __nv_bfloat16 sAl[128 * SPITCH];
    __shared__ __align__(16) __nv_bfloat16 sBh[128 * SPITCH];
    __shared__ __align__(16) __nv_bfloat16 sBl[128 * SPITCH];

    const int tid = threadIdx.x, lane = tid & 31, warp = tid >> 5;
    const int wm = warp >> 2, wn = warp & 3;
    const int lrow = lane & 15, lcolh = (lane >> 4) * 8;

    for (int kc = 0; kc < K; kc += 32) {
        #pragma unroll
        for (int i = 0; i < 2; i++) {
            int idx = tid + i * 256;
            int r = idx >> 2, g = idx & 3;
            size_t src = (size_t)r * K + kc + g * 8;
            int dst = r * SPITCH + g * 8;
            *(uint4*)&sAh[dst] = *(const uint4*)&Ah[src];
            *(uint4*)&sAl[dst] = *(const uint4*)&Al[src];
            *(uint4*)&sBh[dst] = *(const uint4*)&Bh[src];
            *(uint4*)&sBl[dst] = *(const uint4*)&Bl[src];
        }
        __syncthreads();
        #pragma unroll
        for (int ks = 0; ks < 2; ks++) {
            uint32_t ah[4][4], al[4][4];
            #pragma unroll
            for (int mt = 0; mt < 4; mt++) {
                int ro = (wm * 64 + mt * 16 + lrow) * SPITCH + ks * 16 + lcolh;
                ldm_x4(smem_u32(&sAh[ro]), ah[mt]);
                ldm_x4(smem_u32(&sAl[ro]), al[mt]);
            }
            #pragma unroll
            for (int bt = 0; bt < 2; bt++) {
                uint32_t bh[4], bl[4];
                int ro = (wn * 32 + bt * 16 + lrow) * SPITCH + ks * 16 + lcolh;
                ldm_x4(smem_u32(&sBh[ro]), bh);
                ldm_x4(smem_u32(&sBl[ro]), bl);
                #pragma unroll
                for (int mt = 0; mt < 4; mt++) {
                    mma16816(acc[mt][bt * 2],     ah[mt], bh[0], bh[2]);
                    mma16816(acc[mt][bt * 2],     al[mt], bh[0], bh[2]);
                    mma16816(acc[mt][bt * 2],     ah[mt], bl[0], bl[2]);
                    mma16816(acc[mt][bt * 2 + 1], ah[mt], bh[1], bh[3]);
                    mma16816(acc[mt][bt * 2 + 1], al[mt], bh[1], bh[3]);
                    mma16816(acc[mt][bt * 2 + 1], ah[mt], bl[1], bl[3]);
                }
            }
        }
        __syncthreads();
    }
}

// ---------------------------------------------------------------------------
// conversions
// ---------------------------------------------------------------------------
__global__ __launch_bounds__(256) void conv_act(const float* __restrict__ qx,
                                                const float* __restrict__ kvx)
{
    int idx = blockIdx.x * 256 + threadIdx.x;
    const float* src = blockIdx.y ? kvx : qx;
    __nv_bfloat16* hi = blockIdx.y ? g_akv_hi : g_aq_hi;
    __nv_bfloat16* lo = blockIdx.y ? g_akv_lo : g_aq_lo;
    float x = src[idx];
    __nv_bfloat16 h = __float2bfloat16(x);
    hi[idx] = h;
    lo[idx] = __float2bfloat16(x - __bfloat162float(h));
}

__global__ __launch_bounds__(256) void conv_w(
    const float* __restrict__ Wq, const float* __restrict__ Wk,
    const float* __restrict__ Wv, const float* __restrict__ Wg,
    const float* __restrict__ Wo)
{
    int z = blockIdx.z;
    const float* in; int R, C; __nv_bfloat16 *oh, *ol;
    if (z < 4) {
        in = (z == 0) ? Wq : (z == 1) ? Wk : (z == 2) ? Wv : Wg;
        R = CDIM; C = HD; oh = g_wt_hi + (size_t)z * HD * CDIM; ol = g_wt_lo + (size_t)z * HD * CDIM;
    } else {
        in = Wo; R = HD; C = CDIM; oh = g_wot_hi; ol = g_wot_lo;
    }
    int c0 = blockIdx.x * 32, r0 = blockIdx.y * 32;
    if (c0 >= C || r0 >= R) return;
    __shared__ float t[32][33];
    int tx = threadIdx.x & 31, ty = threadIdx.x >> 5;
    for (int i = ty; i < 32; i += 8) t[i][tx] = in[(size_t)(r0 + i) * C + c0 + tx];
    __syncthreads();
    for (int i = ty; i < 32; i += 8) {
        float x = t[tx][i];
        __nv_bfloat16 h = __float2bfloat16(x);
        size_t o = (size_t)(c0 + i) * R + r0 + tx;
        oh[o] = h;
        ol[o] = __float2bfloat16(x - __bfloat162float(h));
    }
}

// ---------------------------------------------------------------------------
// projection GEMMs: grid (HD/128=8, N_TOK/128=32, 4 mats)
// ---------------------------------------------------------------------------
__global__ __launch_bounds__(256, 2) void mm_proj_tc()
{
    const int mat = blockIdx.z;
    const int m0 = blockIdx.y * 128, n0 = blockIdx.x * 128;
    const __nv_bfloat16* Ah = ((mat == 1 || mat == 2) ? g_akv_hi : g_aq_hi) + (size_t)m0 * CDIM;
    const __nv_bfloat16* Al = ((mat == 1 || mat == 2) ? g_akv_lo : g_aq_lo) + (size_t)m0 * CDIM;
    const __nv_bfloat16* Bh = g_wt_hi + (size_t)mat * HD * CDIM + (size_t)n0 * CDIM;
    const __nv_bfloat16* Bl = g_wt_lo + (size_t)mat * HD * CDIM + (size_t)n0 * CDIM;

    float acc[4][4][4] = {};
    gemm_tc(Ah, Al, Bh, Bl, CDIM, acc);

    const int lane = threadIdx.x & 31, warp = threadIdx.x >> 5;
    const int wm = warp >> 2, wn = warp & 3;
    #pragma unroll
    for (int mt = 0; mt < 4; mt++) {
        #pragma unroll
        for (int nt = 0; nt < 4; nt++) {
            #pragma unroll
            for (int rr = 0; rr < 2; rr++) {
                int m = m0 + wm * 64 + mt * 16 + (lane >> 2) + rr * 8;
                int c = n0 + wn * 32 + nt * 8 + (lane & 3) * 2;
                float v0 = acc[mt][nt][rr * 2], v1 = acc[mt][nt][rr * 2 + 1];
                int hh = c >> 6, d = c & 63;
                if (mat == 0) {
                    float x0 = v0 * 0.125f, x1 = v1 * 0.125f;
                    __nv_bfloat16 b0 = __float2bfloat16(x0), b1 = __float2bfloat16(x1);
                    __nv_bfloat162 ph; ph.x = b0; ph.y = b1;
                    __nv_bfloat162 pl;
                    pl.x = __float2bfloat16(x0 - __bfloat162float(b0));
                    pl.y = __float2bfloat16(x1 - __bfloat162float(b1));
                    size_t o = ((size_t)hh * N_TOK + m) * DHEAD + d;
                    *(__nv_bfloat162*)&g_qh[o] = ph;
                    *(__nv_bfloat162*)&g_ql[o] = pl;
                } else if (mat == 1) {
                    __nv_bfloat16 b0 = __float2bfloat16(v0), b1 = __float2bfloat16(v1);
                    __nv_bfloat162 ph; ph.x = b0; ph.y = b1;
                    __nv_bfloat162 pl;
                    pl.x = __float2bfloat16(v0 - __bfloat162float(b0));
                    pl.y = __float2bfloat16(v1 - __bfloat162float(b1));
                    size_t o = ((size_t)hh * N_TOK + m) * DHEAD + d;
                    *(__nv_bfloat162*)&g_kh[o] = ph;
                    *(__nv_bfloat162*)&g_kl[o] = pl;
                } else if (mat == 2) {
                    __nv_bfloat16 b0 = __float2bfloat16(v0), b1 = __float2bfloat16(v1);
                    size_t o0 = ((size_t)hh * DHEAD + d) * N_TOK + m;
                    size_t o1 = ((size_t)hh * DHEAD + d + 1) * N_TOK + m;
                    g_vth[o0] = b0;
                    g_vth[o1] = b1;
                    g_vtl[o0] = __float2bfloat16(v0 - __bfloat162float(b0));
                    g_vtl[o1] = __float2bfloat16(v1 - __bfloat162float(b1));
                } else {
                    float2 v = make_float2(1.f / (1.f + expf(-v0)), 1.f / (1.f + expf(-v1)));
                    *(float2*)&g_gate[(size_t)m * HD + c] = v;
                }
            }
        }
    }
}

// output GEMM
__global__ __launch_bounds__(256, 2) void mm_out_tc(float* __restrict__ out)
{
    const int m0 = blockIdx.y * 128, n0 = blockIdx.x * 128;
    float acc[4][4][4] = {};
    gemm_tc(g_og_hi + (size_t)m0 * HD, g_og_lo + (size_t)m0 * HD,
            g_wot_hi + (size_t)n0 * HD, g_wot_lo + (size_t)n0 * HD, HD, acc);

    const int lane = threadIdx.x & 31, warp = threadIdx.x >> 5;
    const int wm = warp >> 2, wn = warp & 3;
    #pragma unroll
    for (int mt = 0; mt < 4; mt++) {
        #pragma unroll
        for (int nt = 0; nt < 4; nt++) {
            #pragma unroll
            for (int rr = 0; rr < 2; rr++) {
                int m = m0 + wm * 64 + mt * 16 + (lane >> 2) + rr * 8;
                int c = n0 + wn * 32 + nt * 8 + (lane & 3) * 2;
                *(float2*)&out[(size_t)m * CDIM + c] =
                    make_float2(acc[mt][nt][rr * 2], acc[mt][nt][rr * 2 + 1]);
            }
        }
    }
}

// ---------------------------------------------------------------------------
// tensor-core local attention — epilogue fused with gate multiply + bf16 split
// ---------------------------------------------------------------------------
#define QP 72
#define VP 264

__global__ __launch_bounds__(256) void attn_tc(const float* __restrict__ bias)
{
    __nv_bfloat16* Sb = (__nv_bfloat16*)dyn_smem;
    __nv_bfloat16* sQh = Sb;
    __nv_bfloat16* sQl = Sb + 4608;
    __nv_bfloat16* sKh = Sb + 9216;
    __nv_bfloat16* sKl = Sb + 27648;
    __nv_bfloat16* sVh = Sb + 9216;
    __nv_bfloat16* sVl = Sb + 26112;
    float* sO = (float*)dyn_smem;
    float* pm = (float*)(dyn_smem + 92160);
    float* ps = (float*)(dyn_smem + 92672);

    const int h = blockIdx.x, t = blockIdx.y;
    const int tid = threadIdx.x, lane = tid & 31, warp = tid >> 5;
    const int wm = warp & 3, ch = warp >> 2;
    const int kbase = t * NQ - PADL;
    const int lrow = lane & 15, lcolh = (lane >> 4) * 8;
    const int l4 = lane >> 2, lq = lane & 3;

    {
        const __nv_bfloat16* qh = g_qh + ((size_t)h * N_TOK + t * NQ) * DHEAD;
        const __nv_bfloat16* ql = g_ql + ((size_t)h * N_TOK + t * NQ) * DHEAD;
        #pragma unroll
        for (int i = 0; i < 2; i++) {
            int idx = tid + i * 256;
            int r = idx >> 3, g = idx & 7;
            *(uint4*)&sQh[r * QP + g * 8] = *(const uint4*)&qh[idx * 8];
            *(uint4*)&sQl[r * QP + g * 8] = *(const uint4*)&ql[idx * 8];
        }
        #pragma unroll
        for (int i = 0; i < 8; i++) {
            int idx = tid + i * 256;
            int r = idx >> 3, g = idx & 7;
            int gk = kbase + r;
            uint4 vh = {0, 0, 0, 0}, vl = {0, 0, 0, 0};
            if (gk >= 0 && gk < N_TOK) {
                size_t src = ((size_t)h * N_TOK + gk) * DHEAD + g * 8;
                vh = *(const uint4*)&g_kh[src];
                vl = *(const uint4*)&g_kl[src];
            }
            *(uint4*)&sKh[r * QP + g * 8] = vh;
            *(uint4*)&sKl[r * QP + g * 8] = vl;
        }
    }
    __syncthreads();

    uint32_t ah[4][4], al[4][4];
    #pragma unroll
    for (int kc = 0; kc < 4; kc++) {
        int ro = (wm * 16 + lrow) * QP + kc * 16 + lcolh;
        ldm_x4(smem_u32(&sQh[ro]), ah[kc]);
        ldm_x4(smem_u32(&sQl[ro]), al[kc]);
    }
    float acc[16][4];
    #pragma unroll
    for (int i = 0; i < 16; i++) { acc[i][0] = 0.f; acc[i][1] = 0.f; acc[i][2] = 0.f; acc[i][3] = 0.f; }
    #pragma unroll
    for (int nt = 0; nt < 8; nt++) {
        #pragma unroll
        for (int kc = 0; kc < 4; kc++) {
            uint32_t bh[4], bl[4];
            int ro = (ch * 128 + nt * 16 + lrow) * QP + kc * 16 + lcolh;
            ldm_x4(smem_u32(&sKh[ro]), bh);
            ldm_x4(smem_u32(&sKl[ro]), bl);
            mma16816(acc[2 * nt],     ah[kc], bh[0], bh[2]);
            mma16816(acc[2 * nt],     al[kc], bh[0], bh[2]);
            mma16816(acc[2 * nt],     ah[kc], bl[0], bl[2]);
            mma16816(acc[2 * nt + 1], ah[kc], bh[1], bh[3]);
            mma16816(acc[2 * nt + 1], al[kc], bh[1], bh[3]);
            mma16816(acc[2 * nt + 1], ah[kc], bl[1], bl[3]);
        }
    }

    {
        const int r0 = t * NQ + wm * 16 + l4;
        const int c0 = kbase + ch * 128 + lq * 2;
        #pragma unroll
        for (int nt = 0; nt < 16; nt++) {
            int gc = c0 + nt * 8;
            if (gc >= 0 && gc < N_TOK) {
                float2 b0 = *(const float2*)&bias[(size_t)r0 * N_TOK + gc];
                float2 b1 = *(const float2*)&bias[(size_t)(r0 + 8) * N_TOK + gc];
                acc[nt][0] += b0.x; acc[nt][1] += b0.y;
                acc[nt][2] += b1.x; acc[nt][3] += b1.y;
            }
        }
    }

    const int rloc = wm * 16 + l4;
    float mx0 = -1e30f, mx1 = -1e30f;
    #pragma unroll
    for (int nt = 0; nt < 16; nt++) {
        mx0 = fmaxf(mx0, fmaxf(acc[nt][0], acc[nt][1]));
        mx1 = fmaxf(mx1, fmaxf(acc[nt][2], acc[nt][3]));
    }
    mx0 = fmaxf(mx0, __shfl_xor_sync(0xffffffffu, mx0, 1));
    mx0 = fmaxf(mx0, __shfl_xor_sync(0xffffffffu, mx0, 2));
    mx1 = fmaxf(mx1, __shfl_xor_sync(0xffffffffu, mx1, 1));
    mx1 = fmaxf(mx1, __shfl_xor_sync(0xffffffffu, mx1, 2));
    if (lq == 0) { pm[ch * 64 + rloc] = mx0; pm[ch * 64 + rloc + 8] = mx1; }
    __syncthreads();

    float M0 = fmaxf(pm[rloc], pm[64 + rloc]);
    float M1 = fmaxf(pm[rloc + 8], pm[64 + rloc + 8]);
    float s0 = 0.f, s1 = 0.f;
    #pragma unroll
    for (int nt = 0; nt < 16; nt++) {
        acc[nt][0] = __expf(acc[nt][0] - M0); s0 += acc[nt][0];
        acc[nt][1] = __expf(acc[nt][1] - M0); s0 += acc[nt][1];
        acc[nt][2] = __expf(acc[nt][2] - M1); s1 += acc[nt][2];
        acc[nt][3] = __expf(acc[nt][3] - M1); s1 += acc[nt][3];
    }
    s0 += __shfl_xor_sync(0xffffffffu, s0, 1);
    s0 += __shfl_xor_sync(0xffffffffu, s0, 2);
    s1 += __shfl_xor_sync(0xffffffffu, s1, 1);
    s1 += __shfl_xor_sync(0xffffffffu, s1, 2);
    if (lq == 0) { ps[ch * 64 + rloc] = s0; ps[ch * 64 + rloc + 8] = s1; }

    #pragma unroll
    for (int i = 0; i < 8; i++) {
        int idx = tid + i * 256;
        int d = idx >> 5, g = idx & 31;
        int gk0 = kbase + g * 8;
        uint4 vh = {0, 0, 0, 0}, vl = {0, 0, 0, 0};
        if (gk0 >= 0 && gk0 < N_TOK) {
            size_t src = ((size_t)h * DHEAD + d) * N_TOK + gk0;
            vh = *(const uint4*)&g_vth[src];
            vl = *(const uint4*)&g_vtl[src];
        }
        *(uint4*)&sVh[d * VP + g * 8] = vh;
        *(uint4*)&sVl[d * VP + g * 8] = vl;
    }
    __syncthreads();

    float inv0 = 1.f / (ps[rloc] + ps[64 + rloc]);
    float inv1 = 1.f / (ps[rloc + 8] + ps[64 + rloc + 8]);
    #pragma unroll
    for (int nt = 0; nt < 16; nt++) {
        acc[nt][0] *= inv0; acc[nt][1] *= inv0;
        acc[nt][2] *= inv1; acc[nt][3] *= inv1;
    }

    float oacc[8][4];
    #pragma unroll
    for (int i = 0; i < 8; i++) { oacc[i][0] = 0.f; oacc[i][1] = 0.f; oacc[i][2] = 0.f; oacc[i][3] = 0.f; }
    #pragma unroll
    for (int kc = 0; kc < 8; kc++) {
        uint32_t awh[4], awl[4];
        #pragma unroll
        for (int f = 0; f < 4; f++) {
            int nt = 2 * kc + (f >> 1);
            int j = (f & 1) * 2;
            float x0 = acc[nt][j], x1 = acc[nt][j + 1];
            __nv_bfloat16 b0 = __float2bfloat16(x0), b1 = __float2bfloat16(x1);
            __nv_bfloat162 ph; ph.x = b0; ph.y = b1;
            awh[f] = *(uint32_t*)&ph;
            awl[f] = pack_bf16x2(x0 - __bfloat162float(b0), x1 - __bfloat162float(b1));
        }
        #pragma unroll
        for (int dg = 0; dg < 4; dg++) {
            uint32_t bh[4], bl[4];
            int ro = (dg * 16 + lrow) * VP + ch * 128 + kc * 16 + lcolh;
            ldm_x4(smem_u32(&sVh[ro]), bh);
            ldm_x4(smem_u32(&sVl[ro]), bl);
            mma16816(oacc[2 * dg],     awh, bh[0], bh[2]);
            mma16816(oacc[2 * dg],     awl, bh[0], bh[2]);
            mma16816(oacc[2 * dg],     awh, bl[0], bl[2]);
            mma16816(oacc[2 * dg + 1], awh, bh[1], bh[3]);
            mma16816(oacc[2 * dg + 1], awl, bh[1], bh[3]);
            mma16816(oacc[2 * dg + 1], awh, bl[1], bl[3]);
        }
    }

    // ---- combine halves, multiply by gate, split to bf16 hi/lo, store ----
    __syncthreads();
    if (ch == 1) {
        #pragma unroll
        for (int nt = 0; nt < 8; nt++) {
            int c = nt * 8 + lq * 2;
            sO[(wm * 16 + l4) * 66 + c] = oacc[nt][0];
            sO[(wm * 16 + l4) * 66 + c + 1] = oacc[nt][1];
            sO[(wm * 16 + l4 + 8) * 66 + c] = oacc[nt][2];
            sO[(wm * 16 + l4 + 8) * 66 + c + 1] = oacc[nt][3];
        }
    }
    __syncthreads();
    if (ch == 0) {
        #pragma unroll
        for (int nt = 0; nt < 8; nt++) {
            int r = wm * 16 + l4, c = nt * 8 + lq * 2;
            #pragma unroll
            for (int half = 0; half < 2; half++) {
                int rr = r + half * 8;
                float v0 = oacc[nt][half * 2]     + sO[rr * 66 + c];
                float v1 = oacc[nt][half * 2 + 1] + sO[rr * 66 + c + 1];
                size_t gi = (size_t)(t * NQ + rr) * HD + h * DHEAD + c;
                float2 gt = *(const float2*)&g_gate[gi];
                float x0 = v0 * gt.x, x1 = v1 * gt.y;
                __nv_bfloat16 b0 = __float2bfloat16(x0), b1 = __float2bfloat16(x1);
                __nv_bfloat162 ph; ph.x = b0; ph.y = b1;
                __nv_bfloat162 pl;
                pl.x = __float2bfloat16(x0 - __bfloat162float(b0));
                pl.y = __float2bfloat16(x1 - __bfloat162float(b1));
                *(__nv_bfloat162*)&g_og_hi[gi] = ph;
                *(__nv_bfloat162*)&g_og_lo[gi] = pl;
            }
        }
    }
}

// ---------------------------------------------------------------------------
extern "C" void kernel_launch(void* const* d_in, const int* in_sizes, int n_in,
                              void* d_out, int out_size)
{
    const float* qx   = (const float*)d_in[0];
    const float* kvx  = (const float*)d_in[1];
    const float* bias = (const float*)d_in[2];
    const float* Wq   = (const float*)d_in[3];
    const float* Wk   = (const float*)d_in[4];
    const float* Wv   = (const float*)d_in[5];
    const float* Wg   = (const float*)d_in[6];
    const float* Wo   = (const float*)d_in[7];
    float* out = (float*)d_out;

    static int configured = 0;
    if (!configured) {
        cudaFuncSetAttribute(attn_tc, cudaFuncAttributeMaxDynamicSharedMemorySize, 93184);
        configured = 1;
    }

    conv_act<<<dim3(N_TOK * CDIM / 256, 2), 256>>>(qx, kvx);
    conv_w<<<dim3(32, 32, 5), 256>>>(Wq, Wk, Wv, Wg, Wo);

    mm_proj_tc<<<dim3(HD / 128, N_TOK / 128, 4), 256>>>();

    attn_tc<<<dim3(HEADS, NTRUNK), 256, 93184>>>(bias);

    mm_out_tc<<<dim3(CDIM / 128, N_TOK / 128), 256>>>(out);
}

// round 9
// speedup vs baseline: 1.4064x; 1.0452x over previous
#include <cuda_runtime.h>
#include <cuda_bf16.h>
#include <math.h>
#include <stdint.h>

#define N_TOK 4096
#define CDIM 256
#define HEADS 16
#define DHEAD 64
#define HD 1024
#define NQ 64
#define NKEY 256
#define NTRUNK 64
#define PADL 96

extern __shared__ char dyn_smem[];

// ---------------- scratch (device globals) ----------------
__device__ float g_gate[N_TOK * HD];

__device__ __align__(16) __nv_bfloat16 g_wt_hi[4 * HD * CDIM];   // [mat][n][k]
__device__ __align__(16) __nv_bfloat16 g_wt_lo[4 * HD * CDIM];
__device__ __align__(16) __nv_bfloat16 g_wot_hi[CDIM * HD];      // [n][k]
__device__ __align__(16) __nv_bfloat16 g_wot_lo[CDIM * HD];
__device__ __align__(16) __nv_bfloat16 g_og_hi[N_TOK * HD];
__device__ __align__(16) __nv_bfloat16 g_og_lo[N_TOK * HD];

// attention operands (bf16 hi/lo), q pre-scaled by 1/8
__device__ __align__(16) __nv_bfloat16 g_qh[HEADS * N_TOK * DHEAD];  // [h][n][d]
__device__ __align__(16) __nv_bfloat16 g_ql[HEADS * N_TOK * DHEAD];
__device__ __align__(16) __nv_bfloat16 g_kh[HEADS * N_TOK * DHEAD];  // [h][n][d]
__device__ __align__(16) __nv_bfloat16 g_kl[HEADS * N_TOK * DHEAD];
__device__ __align__(16) __nv_bfloat16 g_vth[HEADS * DHEAD * N_TOK]; // [h][d][n]
__device__ __align__(16) __nv_bfloat16 g_vtl[HEADS * DHEAD * N_TOK];

// ---------------- warp-mma helpers (base PTX ISA) -------
__device__ __forceinline__ uint32_t smem_u32(const void* p) {
    uint32_t a;
    asm("{ .reg .u64 t; cvta.to.shared.u64 t, %1; cvt.u32.u64 %0, t; }" : "=r"(a) : "l"(p));
    return a;
}

__device__ __forceinline__ void ldm_x4(uint32_t addr, uint32_t* r) {
    asm volatile("ldmatrix.sync.aligned.m8n8.x4.shared.b16 {%0,%1,%2,%3}, [%4];"
                 : "=r"(r[0]), "=r"(r[1]), "=r"(r[2]), "=r"(r[3]) : "r"(addr));
}

__device__ __forceinline__ void mma16816(float* c, const uint32_t* a, uint32_t b0, uint32_t b1) {
    asm volatile(
        "mma.sync.aligned.m16n8k16.row.col.f32.bf16.bf16.f32 "
        "{%0,%1,%2,%3}, {%4,%5,%6,%7}, {%8,%9}, {%0,%1,%2,%3};"
        : "+f"(c[0]), "+f"(c[1]), "+f"(c[2]), "+f"(c[3])
        : "r"(a[0]), "r"(a[1]), "r"(a[2]), "r"(a[3]), "r"(b0), "r"(b1));
}

__device__ __forceinline__ uint32_t pack_bf16x2(float x0, float x1) {
    __nv_bfloat162 p;
    p.x = __float2bfloat16(x0);
    p.y = __float2bfloat16(x1);
    return *(uint32_t*)&p;
}

__device__ __forceinline__ void split2(float x0, float x1,
                                       __nv_bfloat162* hi, __nv_bfloat162* lo) {
    __nv_bfloat16 b0 = __float2bfloat16(x0), b1 = __float2bfloat16(x1);
    hi->x = b0; hi->y = b1;
    lo->x = __float2bfloat16(x0 - __bfloat162float(b0));
    lo->y = __float2bfloat16(x1 - __bfloat162float(b1));
}

#define SPITCH 40
#define RGN (128 * SPITCH)

// inner-loop compute on one 32-wide K chunk already resident in sbuf
__device__ __forceinline__ void mma_chunk(
    const __nv_bfloat16* sbuf, int wm, int wn, int lrow, int lcolh, float acc[4][4][4])
{
    #pragma unroll
    for (int ks = 0; ks < 2; ks++) {
        uint32_t ah[4][4], al[4][4];
        #pragma unroll
        for (int mt = 0; mt < 4; mt++) {
            int ro = (wm * 64 + mt * 16 + lrow) * SPITCH + ks * 16 + lcolh;
            ldm_x4(smem_u32(&sbuf[ro]), ah[mt]);
            ldm_x4(smem_u32(&sbuf[RGN + ro]), al[mt]);
        }
        #pragma unroll
        for (int bt = 0; bt < 2; bt++) {
            uint32_t bh[4], bl[4];
            int ro = (wn * 32 + bt * 16 + lrow) * SPITCH + ks * 16 + lcolh;
            ldm_x4(smem_u32(&sbuf[2 * RGN + ro]), bh);
            ldm_x4(smem_u32(&sbuf[3 * RGN + ro]), bl);
            #pragma unroll
            for (int mt = 0; mt < 4; mt++) {
                mma16816(acc[mt][bt * 2],     ah[mt], bh[0], bh[2]);
                mma16816(acc[mt][bt * 2],     al[mt], bh[0], bh[2]);
                mma16816(acc[mt][bt * 2],     ah[mt], bl[0], bl[2]);
                mma16816(acc[mt][bt * 2 + 1], ah[mt], bh[1], bh[3]);
                mma16816(acc[mt][bt * 2 + 1], al[mt], bh[1], bh[3]);
                mma16816(acc[mt][bt * 2 + 1], ah[mt], bl[1], bl[3]);
            }
        }
    }
}

// ---------------------------------------------------------------------------
// weight conversion (transpose + hi/lo split)
// ---------------------------------------------------------------------------
__global__ __launch_bounds__(256) void conv_w(
    const float* __restrict__ Wq, const float* __restrict__ Wk,
    const float* __restrict__ Wv, const float* __restrict__ Wg,
    const float* __restrict__ Wo)
{
    int z = blockIdx.z;
    const float* in; int R, C; __nv_bfloat16 *oh, *ol;
    if (z < 4) {
        in = (z == 0) ? Wq : (z == 1) ? Wk : (z == 2) ? Wv : Wg;
        R = CDIM; C = HD; oh = g_wt_hi + (size_t)z * HD * CDIM; ol = g_wt_lo + (size_t)z * HD * CDIM;
    } else {
        in = Wo; R = HD; C = CDIM; oh = g_wot_hi; ol = g_wot_lo;
    }
    int c0 = blockIdx.x * 32, r0 = blockIdx.y * 32;
    if (c0 >= C || r0 >= R) return;
    __shared__ float t[32][33];
    int tx = threadIdx.x & 31, ty = threadIdx.x >> 5;
    for (int i = ty; i < 32; i += 8) t[i][tx] = in[(size_t)(r0 + i) * C + c0 + tx];
    __syncthreads();
    for (int i = ty; i < 32; i += 8) {
        float x = t[tx][i];
        __nv_bfloat16 h = __float2bfloat16(x);
        size_t o = (size_t)(c0 + i) * R + r0 + tx;
        oh[o] = h;
        ol[o] = __float2bfloat16(x - __bfloat162float(h));
    }
}

// ---------------------------------------------------------------------------
// projection GEMMs: A = fp32 activations (split in-flight), B = bf16 weights.
// grid (HD/128=8, N_TOK/128=32, 4 mats). V epilogue staged via smem transpose.
// ---------------------------------------------------------------------------
#define TPT 136   // transpose pitch (halfwords): 272 B/row, 16B-aligned rows

__global__ __launch_bounds__(256, 2) void mm_proj_tc(
    const float* __restrict__ qx, const float* __restrict__ kvx)
{
    __shared__ __align__(16) __nv_bfloat16 sbuf[4 * RGN];   // 40960 B

    const int mat = blockIdx.z;
    const int m0 = blockIdx.y * 128, n0 = blockIdx.x * 128;
    const float* A = ((mat == 1 || mat == 2) ? kvx : qx) + (size_t)m0 * CDIM;
    const __nv_bfloat16* Bh = g_wt_hi + (size_t)mat * HD * CDIM + (size_t)n0 * CDIM;
    const __nv_bfloat16* Bl = g_wt_lo + (size_t)mat * HD * CDIM + (size_t)n0 * CDIM;

    const int tid = threadIdx.x, lane = tid & 31, warp = tid >> 5;
    const int wm = warp >> 2, wn = warp & 3;
    const int lrow = lane & 15, lcolh = (lane >> 4) * 8;

    float acc[4][4][4] = {};

    for (int kc = 0; kc < CDIM; kc += 32) {
        #pragma unroll
        for (int i = 0; i < 2; i++) {
            int idx = tid + i * 256;
            int r = idx >> 2, g = (idx & 3) * 8;
            // A: fp32 -> bf16 hi/lo split in registers
            const float* src = &A[(size_t)r * CDIM + kc + g];
            float4 x0 = *(const float4*)src;
            float4 x1 = *(const float4*)(src + 4);
            __nv_bfloat162 h2[4], l2[4];
            split2(x0.x, x0.y, &h2[0], &l2[0]);
            split2(x0.z, x0.w, &h2[1], &l2[1]);
            split2(x1.x, x1.y, &h2[2], &l2[2]);
            split2(x1.z, x1.w, &h2[3], &l2[3]);
            int dst = r * SPITCH + g;
            *(uint4*)&sbuf[dst] = *(uint4*)h2;
            *(uint4*)&sbuf[RGN + dst] = *(uint4*)l2;
            // B: bf16 hi/lo direct
            size_t srcb = (size_t)r * CDIM + kc + g;
            *(uint4*)&sbuf[2 * RGN + dst] = *(const uint4*)&Bh[srcb];
            *(uint4*)&sbuf[3 * RGN + dst] = *(const uint4*)&Bl[srcb];
        }
        __syncthreads();
        mma_chunk(sbuf, wm, wn, lrow, lcolh, acc);
        __syncthreads();
    }

    const int l4 = lane >> 2, lq = lane & 3;

    if (mat == 2) {
        // stage transpose through smem, two passes (hi, lo), coalesced stores
        __nv_bfloat16* sT = sbuf;   // 128 x TPT halfwords = 34816 B
        #pragma unroll
        for (int pass = 0; pass < 2; pass++) {
            #pragma unroll
            for (int mt = 0; mt < 4; mt++) {
                #pragma unroll
                for (int nt = 0; nt < 4; nt++) {
                    #pragma unroll
                    for (int rr = 0; rr < 2; rr++) {
                        int ml = wm * 64 + mt * 16 + l4 + rr * 8;
                        int cl = wn * 32 + nt * 8 + lq * 2;
                        float v0 = acc[mt][nt][rr * 2], v1 = acc[mt][nt][rr * 2 + 1];
                        __nv_bfloat16 b0 = __float2bfloat16(v0), b1 = __float2bfloat16(v1);
                        if (pass == 0) {
                            sT[cl * TPT + ml] = b0;
                            sT[(cl + 1) * TPT + ml] = b1;
                        } else {
                            sT[cl * TPT + ml] = __float2bfloat16(v0 - __bfloat162float(b0));
                            sT[(cl + 1) * TPT + ml] = __float2bfloat16(v1 - __bfloat162float(b1));
                        }
                    }
                }
            }
            __syncthreads();
            {
                int cl = tid >> 1, half = tid & 1;
                int hh = (n0 + cl) >> 6, d = (n0 + cl) & 63;
                __nv_bfloat16* dst = (pass == 0 ? g_vth : g_vtl)
                                   + ((size_t)hh * DHEAD + d) * N_TOK + m0 + half * 64;
                const __nv_bfloat16* srcr = &sT[cl * TPT + half * 64];
                #pragma unroll
                for (int j = 0; j < 8; j++)
                    *(uint4*)&dst[j * 8] = *(const uint4*)&srcr[j * 8];
            }
            __syncthreads();
        }
        return;
    }

    #pragma unroll
    for (int mt = 0; mt < 4; mt++) {
        #pragma unroll
        for (int nt = 0; nt < 4; nt++) {
            #pragma unroll
            for (int rr = 0; rr < 2; rr++) {
                int m = m0 + wm * 64 + mt * 16 + l4 + rr * 8;
                int c = n0 + wn * 32 + nt * 8 + lq * 2;
                float v0 = acc[mt][nt][rr * 2], v1 = acc[mt][nt][rr * 2 + 1];
                int hh = c >> 6, d = c & 63;
                if (mat == 0) {
                    __nv_bfloat162 ph, pl;
                    split2(v0 * 0.125f, v1 * 0.125f, &ph, &pl);
                    size_t o = ((size_t)hh * N_TOK + m) * DHEAD + d;
                    *(__nv_bfloat162*)&g_qh[o] = ph;
                    *(__nv_bfloat162*)&g_ql[o] = pl;
                } else if (mat == 1) {
                    __nv_bfloat162 ph, pl;
                    split2(v0, v1, &ph, &pl);
                    size_t o = ((size_t)hh * N_TOK + m) * DHEAD + d;
                    *(__nv_bfloat162*)&g_kh[o] = ph;
                    *(__nv_bfloat162*)&g_kl[o] = pl;
                } else {
                    float2 v = make_float2(1.f / (1.f + expf(-v0)), 1.f / (1.f + expf(-v1)));
                    *(float2*)&g_gate[(size_t)m * HD + c] = v;
                }
            }
        }
    }
}

// ---------------------------------------------------------------------------
// output GEMM: A = og bf16 hi/lo, B = Wo^T bf16 hi/lo
// ---------------------------------------------------------------------------
__global__ __launch_bounds__(256, 2) void mm_out_tc(float* __restrict__ out)
{
    __shared__ __align__(16) __nv_bfloat16 sbuf[4 * RGN];

    const int m0 = blockIdx.y * 128, n0 = blockIdx.x * 128;
    const __nv_bfloat16* Ah = g_og_hi + (size_t)m0 * HD;
    const __nv_bfloat16* Al = g_og_lo + (size_t)m0 * HD;
    const __nv_bfloat16* Bh = g_wot_hi + (size_t)n0 * HD;
    const __nv_bfloat16* Bl = g_wot_lo + (size_t)n0 * HD;

    const int tid = threadIdx.x, lane = tid & 31, warp = tid >> 5;
    const int wm = warp >> 2, wn = warp & 3;
    const int lrow = lane & 15, lcolh = (lane >> 4) * 8;

    float acc[4][4][4] = {};

    for (int kc = 0; kc < HD; kc += 32) {
        #pragma unroll
        for (int i = 0; i < 2; i++) {
            int idx = tid + i * 256;
            int r = idx >> 2, g = (idx & 3) * 8;
            size_t src = (size_t)r * HD + kc + g;
            int dst = r * SPITCH + g;
            *(uint4*)&sbuf[dst] = *(const uint4*)&Ah[src];
            *(uint4*)&sbuf[RGN + dst] = *(const uint4*)&Al[src];
            *(uint4*)&sbuf[2 * RGN + dst] = *(const uint4*)&Bh[src];
            *(uint4*)&sbuf[3 * RGN + dst] = *(const uint4*)&Bl[src];
        }
        __syncthreads();
        mma_chunk(sbuf, wm, wn, lrow, lcolh, acc);
        __syncthreads();
    }

    const int l4 = lane >> 2, lq = lane & 3;
    #pragma unroll
    for (int mt = 0; mt < 4; mt++) {
        #pragma unroll
        for (int nt = 0; nt < 4; nt++) {
            #pragma unroll
            for (int rr = 0; rr < 2; rr++) {
                int m = m0 + wm * 64 + mt * 16 + l4 + rr * 8;
                int c = n0 + wn * 32 + nt * 8 + lq * 2;
                *(float2*)&out[(size_t)m * CDIM + c] =
                    make_float2(acc[mt][nt][rr * 2], acc[mt][nt][rr * 2 + 1]);
            }
        }
    }
}

// ---------------------------------------------------------------------------
// tensor-core local attention — epilogue fused with gate multiply + bf16 split
// ---------------------------------------------------------------------------
#define QP 72
#define VP 264

__global__ __launch_bounds__(256) void attn_tc(const float* __restrict__ bias)
{
    __nv_bfloat16* Sb = (__nv_bfloat16*)dyn_smem;
    __nv_bfloat16* sQh = Sb;
    __nv_bfloat16* sQl = Sb + 4608;
    __nv_bfloat16* sKh = Sb + 9216;
    __nv_bfloat16* sKl = Sb + 27648;
    __nv_bfloat16* sVh = Sb + 9216;
    __nv_bfloat16* sVl = Sb + 26112;
    float* sO = (float*)dyn_smem;
    float* pm = (float*)(dyn_smem + 92160);
    float* ps = (float*)(dyn_smem + 92672);

    const int h = blockIdx.x, t = blockIdx.y;
    const int tid = threadIdx.x, lane = tid & 31, warp = tid >> 5;
    const int wm = warp & 3, ch = warp >> 2;
    const int kbase = t * NQ - PADL;
    const int lrow = lane & 15, lcolh = (lane >> 4) * 8;
    const int l4 = lane >> 2, lq = lane & 3;

    {
        const __nv_bfloat16* qh = g_qh + ((size_t)h * N_TOK + t * NQ) * DHEAD;
        const __nv_bfloat16* ql = g_ql + ((size_t)h * N_TOK + t * NQ) * DHEAD;
        #pragma unroll
        for (int i = 0; i < 2; i++) {
            int idx = tid + i * 256;
            int r = idx >> 3, g = idx & 7;
            *(uint4*)&sQh[r * QP + g * 8] = *(const uint4*)&qh[idx * 8];
            *(uint4*)&sQl[r * QP + g * 8] = *(const uint4*)&ql[idx * 8];
        }
        #pragma unroll
        for (int i = 0; i < 8; i++) {
            int idx = tid + i * 256;
            int r = idx >> 3, g = idx & 7;
            int gk = kbase + r;
            uint4 vh = {0, 0, 0, 0}, vl = {0, 0, 0, 0};
            if (gk >= 0 && gk < N_TOK) {
                size_t src = ((size_t)h * N_TOK + gk) * DHEAD + g * 8;
                vh = *(const uint4*)&g_kh[src];
                vl = *(const uint4*)&g_kl[src];
            }
            *(uint4*)&sKh[r * QP + g * 8] = vh;
            *(uint4*)&sKl[r * QP + g * 8] = vl;
        }
    }
    __syncthreads();

    uint32_t ah[4][4], al[4][4];
    #pragma unroll
    for (int kc = 0; kc < 4; kc++) {
        int ro = (wm * 16 + lrow) * QP + kc * 16 + lcolh;
        ldm_x4(smem_u32(&sQh[ro]), ah[kc]);
        ldm_x4(smem_u32(&sQl[ro]), al[kc]);
    }
    float acc[16][4];
    #pragma unroll
    for (int i = 0; i < 16; i++) { acc[i][0] = 0.f; acc[i][1] = 0.f; acc[i][2] = 0.f; acc[i][3] = 0.f; }
    #pragma unroll
    for (int nt = 0; nt < 8; nt++) {
        #pragma unroll
        for (int kc = 0; kc < 4; kc++) {
            uint32_t bh[4], bl[4];
            int ro = (ch * 128 + nt * 16 + lrow) * QP + kc * 16 + lcolh;
            ldm_x4(smem_u32(&sKh[ro]), bh);
            ldm_x4(smem_u32(&sKl[ro]), bl);
            mma16816(acc[2 * nt],     ah[kc], bh[0], bh[2]);
            mma16816(acc[2 * nt],     al[kc], bh[0], bh[2]);
            mma16816(acc[2 * nt],     ah[kc], bl[0], bl[2]);
            mma16816(acc[2 * nt + 1], ah[kc], bh[1], bh[3]);
            mma16816(acc[2 * nt + 1], al[kc], bh[1], bh[3]);
            mma16816(acc[2 * nt + 1], ah[kc], bl[1], bl[3]);
        }
    }

    {
        const int r0 = t * NQ + wm * 16 + l4;
        const int c0 = kbase + ch * 128 + lq * 2;
        #pragma unroll
        for (int nt = 0; nt < 16; nt++) {
            int gc = c0 + nt * 8;
            if (gc >= 0 && gc < N_TOK) {
                float2 b0 = *(const float2*)&bias[(size_t)r0 * N_TOK + gc];
                float2 b1 = *(const float2*)&bias[(size_t)(r0 + 8) * N_TOK + gc];
                acc[nt][0] += b0.x; acc[nt][1] += b0.y;
                acc[nt][2] += b1.x; acc[nt][3] += b1.y;
            }
        }
    }

    const int rloc = wm * 16 + l4;
    float mx0 = -1e30f, mx1 = -1e30f;
    #pragma unroll
    for (int nt = 0; nt < 16; nt++) {
        mx0 = fmaxf(mx0, fmaxf(acc[nt][0], acc[nt][1]));
        mx1 = fmaxf(mx1, fmaxf(acc[nt][2], acc[nt][3]));
    }
    mx0 = fmaxf(mx0, __shfl_xor_sync(0xffffffffu, mx0, 1));
    mx0 = fmaxf(mx0, __shfl_xor_sync(0xffffffffu, mx0, 2));
    mx1 = fmaxf(mx1, __shfl_xor_sync(0xffffffffu, mx1, 1));
    mx1 = fmaxf(mx1, __shfl_xor_sync(0xffffffffu, mx1, 2));
    if (lq == 0) { pm[ch * 64 + rloc] = mx0; pm[ch * 64 + rloc + 8] = mx1; }
    __syncthreads();

    float M0 = fmaxf(pm[rloc], pm[64 + rloc]);
    float M1 = fmaxf(pm[rloc + 8], pm[64 + rloc + 8]);
    float s0 = 0.f, s1 = 0.f;
    #pragma unroll
    for (int nt = 0; nt < 16; nt++) {
        acc[nt][0] = __expf(acc[nt][0] - M0); s0 += acc[nt][0];
        acc[nt][1] = __expf(acc[nt][1] - M0); s0 += acc[nt][1];
        acc[nt][2] = __expf(acc[nt][2] - M1); s1 += acc[nt][2];
        acc[nt][3] = __expf(acc[nt][3] - M1); s1 += acc[nt][3];
    }
    s0 += __shfl_xor_sync(0xffffffffu, s0, 1);
    s0 += __shfl_xor_sync(0xffffffffu, s0, 2);
    s1 += __shfl_xor_sync(0xffffffffu, s1, 1);
    s1 += __shfl_xor_sync(0xffffffffu, s1, 2);
    if (lq == 0) { ps[ch * 64 + rloc] = s0; ps[ch * 64 + rloc + 8] = s1; }

    #pragma unroll
    for (int i = 0; i < 8; i++) {
        int idx = tid + i * 256;
        int d = idx >> 5, g = idx & 31;
        int gk0 = kbase + g * 8;
        uint4 vh = {0, 0, 0, 0}, vl = {0, 0, 0, 0};
        if (gk0 >= 0 && gk0 < N_TOK) {
            size_t src = ((size_t)h * DHEAD + d) * N_TOK + gk0;
            vh = *(const uint4*)&g_vth[src];
            vl = *(const uint4*)&g_vtl[src];
        }
        *(uint4*)&sVh[d * VP + g * 8] = vh;
        *(uint4*)&sVl[d * VP + g * 8] = vl;
    }
    __syncthreads();

    float inv0 = 1.f / (ps[rloc] + ps[64 + rloc]);
    float inv1 = 1.f / (ps[rloc + 8] + ps[64 + rloc + 8]);
    #pragma unroll
    for (int nt = 0; nt < 16; nt++) {
        acc[nt][0] *= inv0; acc[nt][1] *= inv0;
        acc[nt][2] *= inv1; acc[nt][3] *= inv1;
    }

    float oacc[8][4];
    #pragma unroll
    for (int i = 0; i < 8; i++) { oacc[i][0] = 0.f; oacc[i][1] = 0.f; oacc[i][2] = 0.f; oacc[i][3] = 0.f; }
    #pragma unroll
    for (int kc = 0; kc < 8; kc++) {
        uint32_t awh[4], awl[4];
        #pragma unroll
        for (int f = 0; f < 4; f++) {
            int nt = 2 * kc + (f >> 1);
            int j = (f & 1) * 2;
            float x0 = acc[nt][j], x1 = acc[nt][j + 1];
            __nv_bfloat16 b0 = __float2bfloat16(x0), b1 = __float2bfloat16(x1);
            __nv_bfloat162 ph; ph.x = b0; ph.y = b1;
            awh[f] = *(uint32_t*)&ph;
            awl[f] = pack_bf16x2(x0 - __bfloat162float(b0), x1 - __bfloat162float(b1));
        }
        #pragma unroll
        for (int dg = 0; dg < 4; dg++) {
            uint32_t bh[4], bl[4];
            int ro = (dg * 16 + lrow) * VP + ch * 128 + kc * 16 + lcolh;
            ldm_x4(smem_u32(&sVh[ro]), bh);
            ldm_x4(smem_u32(&sVl[ro]), bl);
            mma16816(oacc[2 * dg],     awh, bh[0], bh[2]);
            mma16816(oacc[2 * dg],     awl, bh[0], bh[2]);
            mma16816(oacc[2 * dg],     awh, bl[0], bl[2]);
            mma16816(oacc[2 * dg + 1], awh, bh[1], bh[3]);
            mma16816(oacc[2 * dg + 1], awl, bh[1], bh[3]);
            mma16816(oacc[2 * dg + 1], awh, bl[1], bl[3]);
        }
    }

    // ---- combine halves, multiply by gate, split to bf16 hi/lo, store ----
    __syncthreads();
    if (ch == 1) {
        #pragma unroll
        for (int nt = 0; nt < 8; nt++) {
            int c = nt * 8 + lq * 2;
            sO[(wm * 16 + l4) * 66 + c] = oacc[nt][0];
            sO[(wm * 16 + l4) * 66 + c + 1] = oacc[nt][1];
            sO[(wm * 16 + l4 + 8) * 66 + c] = oacc[nt][2];
            sO[(wm * 16 + l4 + 8) * 66 + c + 1] = oacc[nt][3];
        }
    }
    __syncthreads();
    if (ch == 0) {
        #pragma unroll
        for (int nt = 0; nt < 8; nt++) {
            int r = wm * 16 + l4, c = nt * 8 + lq * 2;
            #pragma unroll
            for (int half = 0; half < 2; half++) {
                int rr = r + half * 8;
                float v0 = oacc[nt][half * 2]     + sO[rr * 66 + c];
                float v1 = oacc[nt][half * 2 + 1] + sO[rr * 66 + c + 1];
                size_t gi = (size_t)(t * NQ + rr) * HD + h * DHEAD + c;
                float2 gt = *(const float2*)&g_gate[gi];
                __nv_bfloat162 ph, pl;
                split2(v0 * gt.x, v1 * gt.y, &ph, &pl);
                *(__nv_bfloat162*)&g_og_hi[gi] = ph;
                *(__nv_bfloat162*)&g_og_lo[gi] = pl;
            }
        }
    }
}

// ---------------------------------------------------------------------------
extern "C" void kernel_launch(void* const* d_in, const int* in_sizes, int n_in,
                              void* d_out, int out_size)
{
    const float* qx   = (const float*)d_in[0];
    const float* kvx  = (const float*)d_in[1];
    const float* bias = (const float*)d_in[2];
    const float* Wq   = (const float*)d_in[3];
    const float* Wk   = (const float*)d_in[4];
    const float* Wv   = (const float*)d_in[5];
    const float* Wg   = (const float*)d_in[6];
    const float* Wo   = (const float*)d_in[7];
    float* out = (float*)d_out;

    static int configured = 0;
    if (!configured) {
        cudaFuncSetAttribute(attn_tc, cudaFuncAttributeMaxDynamicSharedMemorySize, 93184);
        configured = 1;
    }

    conv_w<<<dim3(32, 32, 5), 256>>>(Wq, Wk, Wv, Wg, Wo);

    mm_proj_tc<<<dim3(HD / 128, N_TOK / 128, 4), 256>>>(qx, kvx);

    attn_tc<<<dim3(HEADS, NTRUNK), 256, 93184>>>(bias);

    mm_out_tc<<<dim3(CDIM / 128, N_TOK / 128), 256>>>(out);
}

// round 10
// speedup vs baseline: 1.6069x; 1.1425x over previous
#include <cuda_runtime.h>
#include <cuda_bf16.h>
#include <math.h>
#include <stdint.h>

#define N_TOK 4096
#define CDIM 256
#define HEADS 16
#define DHEAD 64
#define HD 1024
#define NQ 64
#define NKEY 256
#define NTRUNK 64
#define PADL 96
#define KZ 4

extern __shared__ char dyn_smem[];

// ---------------- scratch (device globals) ----------------
__device__ float g_gate[N_TOK * HD];
__device__ float g_part[KZ * N_TOK * CDIM];   // split-K partials for out GEMM

__device__ __align__(16) __nv_bfloat16 g_wt_hi[4 * HD * CDIM];   // [mat][n][k]
__device__ __align__(16) __nv_bfloat16 g_wt_lo[4 * HD * CDIM];
__device__ __align__(16) __nv_bfloat16 g_wot_hi[CDIM * HD];      // [n][k]
__device__ __align__(16) __nv_bfloat16 g_wot_lo[CDIM * HD];
__device__ __align__(16) __nv_bfloat16 g_og_hi[N_TOK * HD];
__device__ __align__(16) __nv_bfloat16 g_og_lo[N_TOK * HD];

// attention operands (bf16 hi/lo), q pre-scaled by 1/8
__device__ __align__(16) __nv_bfloat16 g_qh[HEADS * N_TOK * DHEAD];  // [h][n][d]
__device__ __align__(16) __nv_bfloat16 g_ql[HEADS * N_TOK * DHEAD];
__device__ __align__(16) __nv_bfloat16 g_kh[HEADS * N_TOK * DHEAD];  // [h][n][d]
__device__ __align__(16) __nv_bfloat16 g_kl[HEADS * N_TOK * DHEAD];
__device__ __align__(16) __nv_bfloat16 g_vth[HEADS * DHEAD * N_TOK]; // [h][d][n]
__device__ __align__(16) __nv_bfloat16 g_vtl[HEADS * DHEAD * N_TOK];

// ---------------- warp-mma helpers (base PTX ISA) -------
__device__ __forceinline__ uint32_t smem_u32(const void* p) {
    uint32_t a;
    asm("{ .reg .u64 t; cvta.to.shared.u64 t, %1; cvt.u32.u64 %0, t; }" : "=r"(a) : "l"(p));
    return a;
}

__device__ __forceinline__ void ldm_x4(uint32_t addr, uint32_t* r) {
    asm volatile("ldmatrix.sync.aligned.m8n8.x4.shared.b16 {%0,%1,%2,%3}, [%4];"
                 : "=r"(r[0]), "=r"(r[1]), "=r"(r[2]), "=r"(r[3]) : "r"(addr));
}

__device__ __forceinline__ void mma16816(float* c, const uint32_t* a, uint32_t b0, uint32_t b1) {
    asm volatile(
        "mma.sync.aligned.m16n8k16.row.col.f32.bf16.bf16.f32 "
        "{%0,%1,%2,%3}, {%4,%5,%6,%7}, {%8,%9}, {%0,%1,%2,%3};"
        : "+f"(c[0]), "+f"(c[1]), "+f"(c[2]), "+f"(c[3])
        : "r"(a[0]), "r"(a[1]), "r"(a[2]), "r"(a[3]), "r"(b0), "r"(b1));
}

__device__ __forceinline__ uint32_t pack_bf16x2(float x0, float x1) {
    __nv_bfloat162 p;
    p.x = __float2bfloat16(x0);
    p.y = __float2bfloat16(x1);
    return *(uint32_t*)&p;
}

__device__ __forceinline__ void split2(float x0, float x1,
                                       __nv_bfloat162* hi, __nv_bfloat162* lo) {
    __nv_bfloat16 b0 = __float2bfloat16(x0), b1 = __float2bfloat16(x1);
    hi->x = b0; hi->y = b1;
    lo->x = __float2bfloat16(x0 - __bfloat162float(b0));
    lo->y = __float2bfloat16(x1 - __bfloat162float(b1));
}

#define SPITCH 40
#define RGN (128 * SPITCH)

// inner-loop compute on one 32-wide K chunk already resident in sbuf
__device__ __forceinline__ void mma_chunk(
    const __nv_bfloat16* sbuf, int wm, int wn, int lrow, int lcolh, float acc[4][4][4])
{
    #pragma unroll
    for (int ks = 0; ks < 2; ks++) {
        uint32_t ah[4][4], al[4][4];
        #pragma unroll
        for (int mt = 0; mt < 4; mt++) {
            int ro = (wm * 64 + mt * 16 + lrow) * SPITCH + ks * 16 + lcolh;
            ldm_x4(smem_u32(&sbuf[ro]), ah[mt]);
            ldm_x4(smem_u32(&sbuf[RGN + ro]), al[mt]);
        }
        #pragma unroll
        for (int bt = 0; bt < 2; bt++) {
            uint32_t bh[4], bl[4];
            int ro = (wn * 32 + bt * 16 + lrow) * SPITCH + ks * 16 + lcolh;
            ldm_x4(smem_u32(&sbuf[2 * RGN + ro]), bh);
            ldm_x4(smem_u32(&sbuf[3 * RGN + ro]), bl);
            #pragma unroll
            for (int mt = 0; mt < 4; mt++) {
                mma16816(acc[mt][bt * 2],     ah[mt], bh[0], bh[2]);
                mma16816(acc[mt][bt * 2],     al[mt], bh[0], bh[2]);
                mma16816(acc[mt][bt * 2],     ah[mt], bl[0], bl[2]);
                mma16816(acc[mt][bt * 2 + 1], ah[mt], bh[1], bh[3]);
                mma16816(acc[mt][bt * 2 + 1], al[mt], bh[1], bh[3]);
                mma16816(acc[mt][bt * 2 + 1], ah[mt], bl[1], bl[3]);
            }
        }
    }
}

// ---------------------------------------------------------------------------
// weight conversion (transpose + hi/lo split)
// ---------------------------------------------------------------------------
__global__ __launch_bounds__(256) void conv_w(
    const float* __restrict__ Wq, const float* __restrict__ Wk,
    const float* __restrict__ Wv, const float* __restrict__ Wg,
    const float* __restrict__ Wo)
{
    int z = blockIdx.z;
    const float* in; int R, C; __nv_bfloat16 *oh, *ol;
    if (z < 4) {
        in = (z == 0) ? Wq : (z == 1) ? Wk : (z == 2) ? Wv : Wg;
        R = CDIM; C = HD; oh = g_wt_hi + (size_t)z * HD * CDIM; ol = g_wt_lo + (size_t)z * HD * CDIM;
    } else {
        in = Wo; R = HD; C = CDIM; oh = g_wot_hi; ol = g_wot_lo;
    }
    int c0 = blockIdx.x * 32, r0 = blockIdx.y * 32;
    if (c0 >= C || r0 >= R) return;
    __shared__ float t[32][33];
    int tx = threadIdx.x & 31, ty = threadIdx.x >> 5;
    for (int i = ty; i < 32; i += 8) t[i][tx] = in[(size_t)(r0 + i) * C + c0 + tx];
    __syncthreads();
    for (int i = ty; i < 32; i += 8) {
        float x = t[tx][i];
        __nv_bfloat16 h = __float2bfloat16(x);
        size_t o = (size_t)(c0 + i) * R + r0 + tx;
        oh[o] = h;
        ol[o] = __float2bfloat16(x - __bfloat162float(h));
    }
}

// ---------------------------------------------------------------------------
// projection GEMMs: A = fp32 activations (split in-flight), B = bf16 weights.
// grid (HD/128=8, N_TOK/128=32, 4 mats). V epilogue staged via smem transpose.
// ---------------------------------------------------------------------------
#define TPT 136   // transpose pitch (halfwords): 272 B/row, 16B-aligned rows

__global__ __launch_bounds__(256, 2) void mm_proj_tc(
    const float* __restrict__ qx, const float* __restrict__ kvx)
{
    __shared__ __align__(16) __nv_bfloat16 sbuf[4 * RGN];   // 40960 B

    const int mat = blockIdx.z;
    const int m0 = blockIdx.y * 128, n0 = blockIdx.x * 128;
    const float* A = ((mat == 1 || mat == 2) ? kvx : qx) + (size_t)m0 * CDIM;
    const __nv_bfloat16* Bh = g_wt_hi + (size_t)mat * HD * CDIM + (size_t)n0 * CDIM;
    const __nv_bfloat16* Bl = g_wt_lo + (size_t)mat * HD * CDIM + (size_t)n0 * CDIM;

    const int tid = threadIdx.x, lane = tid & 31, warp = tid >> 5;
    const int wm = warp >> 2, wn = warp & 3;
    const int lrow = lane & 15, lcolh = (lane >> 4) * 8;

    float acc[4][4][4] = {};

    for (int kc = 0; kc < CDIM; kc += 32) {
        #pragma unroll
        for (int i = 0; i < 2; i++) {
            int idx = tid + i * 256;
            int r = idx >> 2, g = (idx & 3) * 8;
            const float* src = &A[(size_t)r * CDIM + kc + g];
            float4 x0 = *(const float4*)src;
            float4 x1 = *(const float4*)(src + 4);
            __nv_bfloat162 h2[4], l2[4];
            split2(x0.x, x0.y, &h2[0], &l2[0]);
            split2(x0.z, x0.w, &h2[1], &l2[1]);
            split2(x1.x, x1.y, &h2[2], &l2[2]);
            split2(x1.z, x1.w, &h2[3], &l2[3]);
            int dst = r * SPITCH + g;
            *(uint4*)&sbuf[dst] = *(uint4*)h2;
            *(uint4*)&sbuf[RGN + dst] = *(uint4*)l2;
            size_t srcb = (size_t)r * CDIM + kc + g;
            *(uint4*)&sbuf[2 * RGN + dst] = *(const uint4*)&Bh[srcb];
            *(uint4*)&sbuf[3 * RGN + dst] = *(const uint4*)&Bl[srcb];
        }
        __syncthreads();
        mma_chunk(sbuf, wm, wn, lrow, lcolh, acc);
        __syncthreads();
    }

    const int l4 = lane >> 2, lq = lane & 3;

    if (mat == 2) {
        __nv_bfloat16* sT = sbuf;   // 128 x TPT halfwords = 34816 B
        #pragma unroll
        for (int pass = 0; pass < 2; pass++) {
            #pragma unroll
            for (int mt = 0; mt < 4; mt++) {
                #pragma unroll
                for (int nt = 0; nt < 4; nt++) {
                    #pragma unroll
                    for (int rr = 0; rr < 2; rr++) {
                        int ml = wm * 64 + mt * 16 + l4 + rr * 8;
                        int cl = wn * 32 + nt * 8 + lq * 2;
                        float v0 = acc[mt][nt][rr * 2], v1 = acc[mt][nt][rr * 2 + 1];
                        __nv_bfloat16 b0 = __float2bfloat16(v0), b1 = __float2bfloat16(v1);
                        if (pass == 0) {
                            sT[cl * TPT + ml] = b0;
                            sT[(cl + 1) * TPT + ml] = b1;
                        } else {
                            sT[cl * TPT + ml] = __float2bfloat16(v0 - __bfloat162float(b0));
                            sT[(cl + 1) * TPT + ml] = __float2bfloat16(v1 - __bfloat162float(b1));
                        }
                    }
                }
            }
            __syncthreads();
            {
                int cl = tid >> 1, half = tid & 1;
                int hh = (n0 + cl) >> 6, d = (n0 + cl) & 63;
                __nv_bfloat16* dst = (pass == 0 ? g_vth : g_vtl)
                                   + ((size_t)hh * DHEAD + d) * N_TOK + m0 + half * 64;
                const __nv_bfloat16* srcr = &sT[cl * TPT + half * 64];
                #pragma unroll
                for (int j = 0; j < 8; j++)
                    *(uint4*)&dst[j * 8] = *(const uint4*)&srcr[j * 8];
            }
            __syncthreads();
        }
        return;
    }

    #pragma unroll
    for (int mt = 0; mt < 4; mt++) {
        #pragma unroll
        for (int nt = 0; nt < 4; nt++) {
            #pragma unroll
            for (int rr = 0; rr < 2; rr++) {
                int m = m0 + wm * 64 + mt * 16 + l4 + rr * 8;
                int c = n0 + wn * 32 + nt * 8 + lq * 2;
                float v0 = acc[mt][nt][rr * 2], v1 = acc[mt][nt][rr * 2 + 1];
                int hh = c >> 6, d = c & 63;
                if (mat == 0) {
                    __nv_bfloat162 ph, pl;
                    split2(v0 * 0.125f, v1 * 0.125f, &ph, &pl);
                    size_t o = ((size_t)hh * N_TOK + m) * DHEAD + d;
                    *(__nv_bfloat162*)&g_qh[o] = ph;
                    *(__nv_bfloat162*)&g_ql[o] = pl;
                } else if (mat == 1) {
                    __nv_bfloat162 ph, pl;
                    split2(v0, v1, &ph, &pl);
                    size_t o = ((size_t)hh * N_TOK + m) * DHEAD + d;
                    *(__nv_bfloat162*)&g_kh[o] = ph;
                    *(__nv_bfloat162*)&g_kl[o] = pl;
                } else {
                    float2 v = make_float2(1.f / (1.f + expf(-v0)), 1.f / (1.f + expf(-v1)));
                    *(float2*)&g_gate[(size_t)m * HD + c] = v;
                }
            }
        }
    }
}

// ---------------------------------------------------------------------------
// output GEMM, split-K: grid (2, 32, KZ). Each CTA does K range of HD/KZ,
// writes fp32 partial tile to g_part[kz]. Reduce kernel sums the slices.
// ---------------------------------------------------------------------------
__global__ __launch_bounds__(256, 2) void mm_out_tc()
{
    __shared__ __align__(16) __nv_bfloat16 sbuf[4 * RGN];

    const int m0 = blockIdx.y * 128, n0 = blockIdx.x * 128;
    const int kz = blockIdx.z;
    const int k0 = kz * (HD / KZ), k1 = k0 + (HD / KZ);
    const __nv_bfloat16* Ah = g_og_hi + (size_t)m0 * HD;
    const __nv_bfloat16* Al = g_og_lo + (size_t)m0 * HD;
    const __nv_bfloat16* Bh = g_wot_hi + (size_t)n0 * HD;
    const __nv_bfloat16* Bl = g_wot_lo + (size_t)n0 * HD;

    const int tid = threadIdx.x, lane = tid & 31, warp = tid >> 5;
    const int wm = warp >> 2, wn = warp & 3;
    const int lrow = lane & 15, lcolh = (lane >> 4) * 8;

    float acc[4][4][4] = {};

    for (int kc = k0; kc < k1; kc += 32) {
        #pragma unroll
        for (int i = 0; i < 2; i++) {
            int idx = tid + i * 256;
            int r = idx >> 2, g = (idx & 3) * 8;
            size_t src = (size_t)r * HD + kc + g;
            int dst = r * SPITCH + g;
            *(uint4*)&sbuf[dst] = *(const uint4*)&Ah[src];
            *(uint4*)&sbuf[RGN + dst] = *(const uint4*)&Al[src];
            *(uint4*)&sbuf[2 * RGN + dst] = *(const uint4*)&Bh[src];
            *(uint4*)&sbuf[3 * RGN + dst] = *(const uint4*)&Bl[src];
        }
        __syncthreads();
        mma_chunk(sbuf, wm, wn, lrow, lcolh, acc);
        __syncthreads();
    }

    float* part = g_part + (size_t)kz * N_TOK * CDIM;
    const int l4 = lane >> 2, lq = lane & 3;
    #pragma unroll
    for (int mt = 0; mt < 4; mt++) {
        #pragma unroll
        for (int nt = 0; nt < 4; nt++) {
            #pragma unroll
            for (int rr = 0; rr < 2; rr++) {
                int m = m0 + wm * 64 + mt * 16 + l4 + rr * 8;
                int c = n0 + wn * 32 + nt * 8 + lq * 2;
                *(float2*)&part[(size_t)m * CDIM + c] =
                    make_float2(acc[mt][nt][rr * 2], acc[mt][nt][rr * 2 + 1]);
            }
        }
    }
}

__global__ __launch_bounds__(256) void reduce_out(float* __restrict__ out)
{
    int idx = (blockIdx.x * 256 + threadIdx.x) * 4;
    float4 a = *(const float4*)&g_part[idx];
    float4 b = *(const float4*)&g_part[N_TOK * CDIM + idx];
    float4 c = *(const float4*)&g_part[2 * N_TOK * CDIM + idx];
    float4 d = *(const float4*)&g_part[3 * N_TOK * CDIM + idx];
    float4 r = make_float4(a.x + b.x + c.x + d.x, a.y + b.y + c.y + d.y,
                           a.z + b.z + c.z + d.z, a.w + b.w + c.w + d.w);
    *(float4*)&out[idx] = r;
}

// ---------------------------------------------------------------------------
// tensor-core local attention — epilogue fused with gate multiply + bf16 split
// ---------------------------------------------------------------------------
#define QP 72
#define VP 264

__global__ __launch_bounds__(256) void attn_tc(const float* __restrict__ bias)
{
    __nv_bfloat16* Sb = (__nv_bfloat16*)dyn_smem;
    __nv_bfloat16* sQh = Sb;
    __nv_bfloat16* sQl = Sb + 4608;
    __nv_bfloat16* sKh = Sb + 9216;
    __nv_bfloat16* sKl = Sb + 27648;
    __nv_bfloat16* sVh = Sb + 9216;
    __nv_bfloat16* sVl = Sb + 26112;
    float* sO = (float*)dyn_smem;
    float* pm = (float*)(dyn_smem + 92160);
    float* ps = (float*)(dyn_smem + 92672);

    const int h = blockIdx.x, t = blockIdx.y;
    const int tid = threadIdx.x, lane = tid & 31, warp = tid >> 5;
    const int wm = warp & 3, ch = warp >> 2;
    const int kbase = t * NQ - PADL;
    const int lrow = lane & 15, lcolh = (lane >> 4) * 8;
    const int l4 = lane >> 2, lq = lane & 3;

    {
        const __nv_bfloat16* qh = g_qh + ((size_t)h * N_TOK + t * NQ) * DHEAD;
        const __nv_bfloat16* ql = g_ql + ((size_t)h * N_TOK + t * NQ) * DHEAD;
        #pragma unroll
        for (int i = 0; i < 2; i++) {
            int idx = tid + i * 256;
            int r = idx >> 3, g = idx & 7;
            *(uint4*)&sQh[r * QP + g * 8] = *(const uint4*)&qh[idx * 8];
            *(uint4*)&sQl[r * QP + g * 8] = *(const uint4*)&ql[idx * 8];
        }
        #pragma unroll
        for (int i = 0; i < 8; i++) {
            int idx = tid + i * 256;
            int r = idx >> 3, g = idx & 7;
            int gk = kbase + r;
            uint4 vh = {0, 0, 0, 0}, vl = {0, 0, 0, 0};
            if (gk >= 0 && gk < N_TOK) {
                size_t src = ((size_t)h * N_TOK + gk) * DHEAD + g * 8;
                vh = *(const uint4*)&g_kh[src];
                vl = *(const uint4*)&g_kl[src];
            }
            *(uint4*)&sKh[r * QP + g * 8] = vh;
            *(uint4*)&sKl[r * QP + g * 8] = vl;
        }
    }
    __syncthreads();

    uint32_t ah[4][4], al[4][4];
    #pragma unroll
    for (int kc = 0; kc < 4; kc++) {
        int ro = (wm * 16 + lrow) * QP + kc * 16 + lcolh;
        ldm_x4(smem_u32(&sQh[ro]), ah[kc]);
        ldm_x4(smem_u32(&sQl[ro]), al[kc]);
    }
    float acc[16][4];
    #pragma unroll
    for (int i = 0; i < 16; i++) { acc[i][0] = 0.f; acc[i][1] = 0.f; acc[i][2] = 0.f; acc[i][3] = 0.f; }
    #pragma unroll
    for (int nt = 0; nt < 8; nt++) {
        #pragma unroll
        for (int kc = 0; kc < 4; kc++) {
            uint32_t bh[4], bl[4];
            int ro = (ch * 128 + nt * 16 + lrow) * QP + kc * 16 + lcolh;
            ldm_x4(smem_u32(&sKh[ro]), bh);
            ldm_x4(smem_u32(&sKl[ro]), bl);
            mma16816(acc[2 * nt],     ah[kc], bh[0], bh[2]);
            mma16816(acc[2 * nt],     al[kc], bh[0], bh[2]);
            mma16816(acc[2 * nt],     ah[kc], bl[0], bl[2]);
            mma16816(acc[2 * nt + 1], ah[kc], bh[1], bh[3]);
            mma16816(acc[2 * nt + 1], al[kc], bh[1], bh[3]);
            mma16816(acc[2 * nt + 1], ah[kc], bl[1], bl[3]);
        }
    }

    {
        const int r0 = t * NQ + wm * 16 + l4;
        const int c0 = kbase + ch * 128 + lq * 2;
        #pragma unroll
        for (int nt = 0; nt < 16; nt++) {
            int gc = c0 + nt * 8;
            if (gc >= 0 && gc < N_TOK) {
                float2 b0 = *(const float2*)&bias[(size_t)r0 * N_TOK + gc];
                float2 b1 = *(const float2*)&bias[(size_t)(r0 + 8) * N_TOK + gc];
                acc[nt][0] += b0.x; acc[nt][1] += b0.y;
                acc[nt][2] += b1.x; acc[nt][3] += b1.y;
            }
        }
    }

    const int rloc = wm * 16 + l4;
    float mx0 = -1e30f, mx1 = -1e30f;
    #pragma unroll
    for (int nt = 0; nt < 16; nt++) {
        mx0 = fmaxf(mx0, fmaxf(acc[nt][0], acc[nt][1]));
        mx1 = fmaxf(mx1, fmaxf(acc[nt][2], acc[nt][3]));
    }
    mx0 = fmaxf(mx0, __shfl_xor_sync(0xffffffffu, mx0, 1));
    mx0 = fmaxf(mx0, __shfl_xor_sync(0xffffffffu, mx0, 2));
    mx1 = fmaxf(mx1, __shfl_xor_sync(0xffffffffu, mx1, 1));
    mx1 = fmaxf(mx1, __shfl_xor_sync(0xffffffffu, mx1, 2));
    if (lq == 0) { pm[ch * 64 + rloc] = mx0; pm[ch * 64 + rloc + 8] = mx1; }
    __syncthreads();

    float M0 = fmaxf(pm[rloc], pm[64 + rloc]);
    float M1 = fmaxf(pm[rloc + 8], pm[64 + rloc + 8]);
    float s0 = 0.f, s1 = 0.f;
    #pragma unroll
    for (int nt = 0; nt < 16; nt++) {
        acc[nt][0] = __expf(acc[nt][0] - M0); s0 += acc[nt][0];
        acc[nt][1] = __expf(acc[nt][1] - M0); s0 += acc[nt][1];
        acc[nt][2] = __expf(acc[nt][2] - M1); s1 += acc[nt][2];
        acc[nt][3] = __expf(acc[nt][3] - M1); s1 += acc[nt][3];
    }
    s0 += __shfl_xor_sync(0xffffffffu, s0, 1);
    s0 += __shfl_xor_sync(0xffffffffu, s0, 2);
    s1 += __shfl_xor_sync(0xffffffffu, s1, 1);
    s1 += __shfl_xor_sync(0xffffffffu, s1, 2);
    if (lq == 0) { ps[ch * 64 + rloc] = s0; ps[ch * 64 + rloc + 8] = s1; }

    #pragma unroll
    for (int i = 0; i < 8; i++) {
        int idx = tid + i * 256;
        int d = idx >> 5, g = idx & 31;
        int gk0 = kbase + g * 8;
        uint4 vh = {0, 0, 0, 0}, vl = {0, 0, 0, 0};
        if (gk0 >= 0 && gk0 < N_TOK) {
            size_t src = ((size_t)h * DHEAD + d) * N_TOK + gk0;
            vh = *(const uint4*)&g_vth[src];
            vl = *(const uint4*)&g_vtl[src];
        }
        *(uint4*)&sVh[d * VP + g * 8] = vh;
        *(uint4*)&sVl[d * VP + g * 8] = vl;
    }
    __syncthreads();

    float inv0 = 1.f / (ps[rloc] + ps[64 + rloc]);
    float inv1 = 1.f / (ps[rloc + 8] + ps[64 + rloc + 8]);
    #pragma unroll
    for (int nt = 0; nt < 16; nt++) {
        acc[nt][0] *= inv0; acc[nt][1] *= inv0;
        acc[nt][2] *= inv1; acc[nt][3] *= inv1;
    }

    float oacc[8][4];
    #pragma unroll
    for (int i = 0; i < 8; i++) { oacc[i][0] = 0.f; oacc[i][1] = 0.f; oacc[i][2] = 0.f; oacc[i][3] = 0.f; }
    #pragma unroll
    for (int kc = 0; kc < 8; kc++) {
        uint32_t awh[4], awl[4];
        #pragma unroll
        for (int f = 0; f < 4; f++) {
            int nt = 2 * kc + (f >> 1);
            int j = (f & 1) * 2;
            float x0 = acc[nt][j], x1 = acc[nt][j + 1];
            __nv_bfloat16 b0 = __float2bfloat16(x0), b1 = __float2bfloat16(x1);
            __nv_bfloat162 ph; ph.x = b0; ph.y = b1;
            awh[f] = *(uint32_t*)&ph;
            awl[f] = pack_bf16x2(x0 - __bfloat162float(b0), x1 - __bfloat162float(b1));
        }
        #pragma unroll
        for (int dg = 0; dg < 4; dg++) {
            uint32_t bh[4], bl[4];
            int ro = (dg * 16 + lrow) * VP + ch * 128 + kc * 16 + lcolh;
            ldm_x4(smem_u32(&sVh[ro]), bh);
            ldm_x4(smem_u32(&sVl[ro]), bl);
            mma16816(oacc[2 * dg],     awh, bh[0], bh[2]);
            mma16816(oacc[2 * dg],     awl, bh[0], bh[2]);
            mma16816(oacc[2 * dg],     awh, bl[0], bl[2]);
            mma16816(oacc[2 * dg + 1], awh, bh[1], bh[3]);
            mma16816(oacc[2 * dg + 1], awl, bh[1], bh[3]);
            mma16816(oacc[2 * dg + 1], awh, bl[1], bl[3]);
        }
    }

    // ---- combine halves, multiply by gate, split to bf16 hi/lo, store ----
    __syncthreads();
    if (ch == 1) {
        #pragma unroll
        for (int nt = 0; nt < 8; nt++) {
            int c = nt * 8 + lq * 2;
            sO[(wm * 16 + l4) * 66 + c] = oacc[nt][0];
            sO[(wm * 16 + l4) * 66 + c + 1] = oacc[nt][1];
            sO[(wm * 16 + l4 + 8) * 66 + c] = oacc[nt][2];
            sO[(wm * 16 + l4 + 8) * 66 + c + 1] = oacc[nt][3];
        }
    }
    __syncthreads();
    if (ch == 0) {
        #pragma unroll
        for (int nt = 0; nt < 8; nt++) {
            int r = wm * 16 + l4, c = nt * 8 + lq * 2;
            #pragma unroll
            for (int half = 0; half < 2; half++) {
                int rr = r + half * 8;
                float v0 = oacc[nt][half * 2]     + sO[rr * 66 + c];
                float v1 = oacc[nt][half * 2 + 1] + sO[rr * 66 + c + 1];
                size_t gi = (size_t)(t * NQ + rr) * HD + h * DHEAD + c;
                float2 gt = *(const float2*)&g_gate[gi];
                __nv_bfloat162 ph, pl;
                split2(v0 * gt.x, v1 * gt.y, &ph, &pl);
                *(__nv_bfloat162*)&g_og_hi[gi] = ph;
                *(__nv_bfloat162*)&g_og_lo[gi] = pl;
            }
        }
    }
}

// ---------------------------------------------------------------------------
extern "C" void kernel_launch(void* const* d_in, const int* in_sizes, int n_in,
                              void* d_out, int out_size)
{
    const float* qx   = (const float*)d_in[0];
    const float* kvx  = (const float*)d_in[1];
    const float* bias = (const float*)d_in[2];
    const float* Wq   = (const float*)d_in[3];
    const float* Wk   = (const float*)d_in[4];
    const float* Wv   = (const float*)d_in[5];
    const float* Wg   = (const float*)d_in[6];
    const float* Wo   = (const float*)d_in[7];
    float* out = (float*)d_out;

    static int configured = 0;
    if (!configured) {
        cudaFuncSetAttribute(attn_tc, cudaFuncAttributeMaxDynamicSharedMemorySize, 93184);
        configured = 1;
    }

    conv_w<<<dim3(32, 32, 5), 256>>>(Wq, Wk, Wv, Wg, Wo);

    mm_proj_tc<<<dim3(HD / 128, N_TOK / 128, 4), 256>>>(qx, kvx);

    attn_tc<<<dim3(HEADS, NTRUNK), 256, 93184>>>(bias);

    mm_out_tc<<<dim3(CDIM / 128, N_TOK / 128, KZ), 256>>>();
    reduce_out<<<N_TOK * CDIM / 1024, 256>>>(out);
}

// round 11
// speedup vs baseline: 1.6843x; 1.0482x over previous
#include <cuda_runtime.h>
#include <cuda_bf16.h>
#include <math.h>
#include <stdint.h>

#define N_TOK 4096
#define CDIM 256
#define HEADS 16
#define DHEAD 64
#define HD 1024
#define NQ 64
#define NKEY 256
#define NTRUNK 64
#define PADL 96
#define KZ 4

extern __shared__ char dyn_smem[];

// ---------------- scratch (device globals) ----------------
__device__ float g_gate[N_TOK * HD];
__device__ float g_part[KZ * N_TOK * CDIM];   // split-K partials for out GEMM

__device__ __align__(16) __nv_bfloat16 g_wt_hi[4 * HD * CDIM];   // [mat][n][k]
__device__ __align__(16) __nv_bfloat16 g_wt_lo[4 * HD * CDIM];
__device__ __align__(16) __nv_bfloat16 g_wot_hi[CDIM * HD];      // [n][k]
__device__ __align__(16) __nv_bfloat16 g_wot_lo[CDIM * HD];
__device__ __align__(16) __nv_bfloat16 g_og_hi[N_TOK * HD];
__device__ __align__(16) __nv_bfloat16 g_og_lo[N_TOK * HD];

// attention operands (bf16 hi/lo), q pre-scaled by 1/8
__device__ __align__(16) __nv_bfloat16 g_qh[HEADS * N_TOK * DHEAD];  // [h][n][d]
__device__ __align__(16) __nv_bfloat16 g_ql[HEADS * N_TOK * DHEAD];
__device__ __align__(16) __nv_bfloat16 g_kh[HEADS * N_TOK * DHEAD];  // [h][n][d]
__device__ __align__(16) __nv_bfloat16 g_kl[HEADS * N_TOK * DHEAD];
__device__ __align__(16) __nv_bfloat16 g_vth[HEADS * DHEAD * N_TOK]; // [h][d][n]
__device__ __align__(16) __nv_bfloat16 g_vtl[HEADS * DHEAD * N_TOK];

// ---------------- warp-mma helpers (base PTX ISA) -------
__device__ __forceinline__ uint32_t smem_u32(const void* p) {
    uint32_t a;
    asm("{ .reg .u64 t; cvta.to.shared.u64 t, %1; cvt.u32.u64 %0, t; }" : "=r"(a) : "l"(p));
    return a;
}

__device__ __forceinline__ void ldm_x4(uint32_t addr, uint32_t* r) {
    asm volatile("ldmatrix.sync.aligned.m8n8.x4.shared.b16 {%0,%1,%2,%3}, [%4];"
                 : "=r"(r[0]), "=r"(r[1]), "=r"(r[2]), "=r"(r[3]) : "r"(addr));
}

__device__ __forceinline__ void mma16816(float* c, const uint32_t* a, uint32_t b0, uint32_t b1) {
    asm volatile(
        "mma.sync.aligned.m16n8k16.row.col.f32.bf16.bf16.f32 "
        "{%0,%1,%2,%3}, {%4,%5,%6,%7}, {%8,%9}, {%0,%1,%2,%3};"
        : "+f"(c[0]), "+f"(c[1]), "+f"(c[2]), "+f"(c[3])
        : "r"(a[0]), "r"(a[1]), "r"(a[2]), "r"(a[3]), "r"(b0), "r"(b1));
}

__device__ __forceinline__ uint32_t pack_bf16x2(float x0, float x1) {
    __nv_bfloat162 p;
    p.x = __float2bfloat16(x0);
    p.y = __float2bfloat16(x1);
    return *(uint32_t*)&p;
}

__device__ __forceinline__ void split2(float x0, float x1,
                                       __nv_bfloat162* hi, __nv_bfloat162* lo) {
    __nv_bfloat16 b0 = __float2bfloat16(x0), b1 = __float2bfloat16(x1);
    hi->x = b0; hi->y = b1;
    lo->x = __float2bfloat16(x0 - __bfloat162float(b0));
    lo->y = __float2bfloat16(x1 - __bfloat162float(b1));
}

// GEMM smem: BK=64 chunks, pitch 72 halfwords (conflict-free ldmatrix),
// 4 regions (Ah, Al, Bh, Bl) of 128x72 halfwords = 18432 B each -> 73728 B.
#define SPITCH 72
#define RGN (128 * SPITCH)
#define SMEM_GEMM (4 * RGN * 2)

// compute on one 64-wide K chunk resident in sbuf
__device__ __forceinline__ void mma_chunk64(
    const __nv_bfloat16* sbuf, int wm, int wn, int lrow, int lcolh, float acc[4][4][4])
{
    #pragma unroll
    for (int ks = 0; ks < 4; ks++) {
        uint32_t ah[4][4], al[4][4];
        #pragma unroll
        for (int mt = 0; mt < 4; mt++) {
            int ro = (wm * 64 + mt * 16 + lrow) * SPITCH + ks * 16 + lcolh;
            ldm_x4(smem_u32(&sbuf[ro]), ah[mt]);
            ldm_x4(smem_u32(&sbuf[RGN + ro]), al[mt]);
        }
        #pragma unroll
        for (int bt = 0; bt < 2; bt++) {
            uint32_t bh[4], bl[4];
            int ro = (wn * 32 + bt * 16 + lrow) * SPITCH + ks * 16 + lcolh;
            ldm_x4(smem_u32(&sbuf[2 * RGN + ro]), bh);
            ldm_x4(smem_u32(&sbuf[3 * RGN + ro]), bl);
            #pragma unroll
            for (int mt = 0; mt < 4; mt++) {
                mma16816(acc[mt][bt * 2],     ah[mt], bh[0], bh[2]);
                mma16816(acc[mt][bt * 2],     al[mt], bh[0], bh[2]);
                mma16816(acc[mt][bt * 2],     ah[mt], bl[0], bl[2]);
                mma16816(acc[mt][bt * 2 + 1], ah[mt], bh[1], bh[3]);
                mma16816(acc[mt][bt * 2 + 1], al[mt], bh[1], bh[3]);
                mma16816(acc[mt][bt * 2 + 1], ah[mt], bl[1], bl[3]);
            }
        }
    }
}

// ---------------------------------------------------------------------------
// weight conversion (transpose + hi/lo split)
// ---------------------------------------------------------------------------
__global__ __launch_bounds__(256) void conv_w(
    const float* __restrict__ Wq, const float* __restrict__ Wk,
    const float* __restrict__ Wv, const float* __restrict__ Wg,
    const float* __restrict__ Wo)
{
    int z = blockIdx.z;
    const float* in; int R, C; __nv_bfloat16 *oh, *ol;
    if (z < 4) {
        in = (z == 0) ? Wq : (z == 1) ? Wk : (z == 2) ? Wv : Wg;
        R = CDIM; C = HD; oh = g_wt_hi + (size_t)z * HD * CDIM; ol = g_wt_lo + (size_t)z * HD * CDIM;
    } else {
        in = Wo; R = HD; C = CDIM; oh = g_wot_hi; ol = g_wot_lo;
    }
    int c0 = blockIdx.x * 32, r0 = blockIdx.y * 32;
    if (c0 >= C || r0 >= R) return;
    __shared__ float t[32][33];
    int tx = threadIdx.x & 31, ty = threadIdx.x >> 5;
    for (int i = ty; i < 32; i += 8) t[i][tx] = in[(size_t)(r0 + i) * C + c0 + tx];
    __syncthreads();
    for (int i = ty; i < 32; i += 8) {
        float x = t[tx][i];
        __nv_bfloat16 h = __float2bfloat16(x);
        size_t o = (size_t)(c0 + i) * R + r0 + tx;
        oh[o] = h;
        ol[o] = __float2bfloat16(x - __bfloat162float(h));
    }
}

// ---------------------------------------------------------------------------
// projection GEMMs: A = fp32 activations (split in-flight), B = bf16 weights.
// grid (HD/128=8, N_TOK/128=32, 4 mats). BK=64 (4 chunk iterations).
// ---------------------------------------------------------------------------
#define TPT 136   // transpose pitch (halfwords): 272 B/row, 16B-aligned rows

__global__ __launch_bounds__(256, 2) void mm_proj_tc(
    const float* __restrict__ qx, const float* __restrict__ kvx)
{
    __nv_bfloat16* sbuf = (__nv_bfloat16*)dyn_smem;

    const int mat = blockIdx.z;
    const int m0 = blockIdx.y * 128, n0 = blockIdx.x * 128;
    const float* A = ((mat == 1 || mat == 2) ? kvx : qx) + (size_t)m0 * CDIM;
    const __nv_bfloat16* Bh = g_wt_hi + (size_t)mat * HD * CDIM + (size_t)n0 * CDIM;
    const __nv_bfloat16* Bl = g_wt_lo + (size_t)mat * HD * CDIM + (size_t)n0 * CDIM;

    const int tid = threadIdx.x, lane = tid & 31, warp = tid >> 5;
    const int wm = warp >> 2, wn = warp & 3;
    const int lrow = lane & 15, lcolh = (lane >> 4) * 8;

    float acc[4][4][4] = {};

    for (int kc = 0; kc < CDIM; kc += 64) {
        #pragma unroll
        for (int i = 0; i < 4; i++) {
            int idx = tid + i * 256;
            int r = idx >> 3, g = (idx & 7) * 8;
            const float* src = &A[(size_t)r * CDIM + kc + g];
            float4 x0 = *(const float4*)src;
            float4 x1 = *(const float4*)(src + 4);
            __nv_bfloat162 h2[4], l2[4];
            split2(x0.x, x0.y, &h2[0], &l2[0]);
            split2(x0.z, x0.w, &h2[1], &l2[1]);
            split2(x1.x, x1.y, &h2[2], &l2[2]);
            split2(x1.z, x1.w, &h2[3], &l2[3]);
            int dst = r * SPITCH + g;
            *(uint4*)&sbuf[dst] = *(uint4*)h2;
            *(uint4*)&sbuf[RGN + dst] = *(uint4*)l2;
            size_t srcb = (size_t)r * CDIM + kc + g;
            *(uint4*)&sbuf[2 * RGN + dst] = *(const uint4*)&Bh[srcb];
            *(uint4*)&sbuf[3 * RGN + dst] = *(const uint4*)&Bl[srcb];
        }
        __syncthreads();
        mma_chunk64(sbuf, wm, wn, lrow, lcolh, acc);
        __syncthreads();
    }

    const int l4 = lane >> 2, lq = lane & 3;

    if (mat == 2) {
        __nv_bfloat16* sT = sbuf;   // 128 x TPT halfwords = 34816 B
        #pragma unroll
        for (int pass = 0; pass < 2; pass++) {
            #pragma unroll
            for (int mt = 0; mt < 4; mt++) {
                #pragma unroll
                for (int nt = 0; nt < 4; nt++) {
                    #pragma unroll
                    for (int rr = 0; rr < 2; rr++) {
                        int ml = wm * 64 + mt * 16 + l4 + rr * 8;
                        int cl = wn * 32 + nt * 8 + lq * 2;
                        float v0 = acc[mt][nt][rr * 2], v1 = acc[mt][nt][rr * 2 + 1];
                        __nv_bfloat16 b0 = __float2bfloat16(v0), b1 = __float2bfloat16(v1);
                        if (pass == 0) {
                            sT[cl * TPT + ml] = b0;
                            sT[(cl + 1) * TPT + ml] = b1;
                        } else {
                            sT[cl * TPT + ml] = __float2bfloat16(v0 - __bfloat162float(b0));
                            sT[(cl + 1) * TPT + ml] = __float2bfloat16(v1 - __bfloat162float(b1));
                        }
                    }
                }
            }
            __syncthreads();
            {
                int cl = tid >> 1, half = tid & 1;
                int hh = (n0 + cl) >> 6, d = (n0 + cl) & 63;
                __nv_bfloat16* dst = (pass == 0 ? g_vth : g_vtl)
                                   + ((size_t)hh * DHEAD + d) * N_TOK + m0 + half * 64;
                const __nv_bfloat16* srcr = &sT[cl * TPT + half * 64];
                #pragma unroll
                for (int j = 0; j < 8; j++)
                    *(uint4*)&dst[j * 8] = *(const uint4*)&srcr[j * 8];
            }
            __syncthreads();
        }
        return;
    }

    #pragma unroll
    for (int mt = 0; mt < 4; mt++) {
        #pragma unroll
        for (int nt = 0; nt < 4; nt++) {
            #pragma unroll
            for (int rr = 0; rr < 2; rr++) {
                int m = m0 + wm * 64 + mt * 16 + l4 + rr * 8;
                int c = n0 + wn * 32 + nt * 8 + lq * 2;
                float v0 = acc[mt][nt][rr * 2], v1 = acc[mt][nt][rr * 2 + 1];
                int hh = c >> 6, d = c & 63;
                if (mat == 0) {
                    __nv_bfloat162 ph, pl;
                    split2(v0 * 0.125f, v1 * 0.125f, &ph, &pl);
                    size_t o = ((size_t)hh * N_TOK + m) * DHEAD + d;
                    *(__nv_bfloat162*)&g_qh[o] = ph;
                    *(__nv_bfloat162*)&g_ql[o] = pl;
                } else if (mat == 1) {
                    __nv_bfloat162 ph, pl;
                    split2(v0, v1, &ph, &pl);
                    size_t o = ((size_t)hh * N_TOK + m) * DHEAD + d;
                    *(__nv_bfloat162*)&g_kh[o] = ph;
                    *(__nv_bfloat162*)&g_kl[o] = pl;
                } else {
                    float2 v = make_float2(1.f / (1.f + expf(-v0)), 1.f / (1.f + expf(-v1)));
                    *(float2*)&g_gate[(size_t)m * HD + c] = v;
                }
            }
        }
    }
}

// ---------------------------------------------------------------------------
// output GEMM, split-K: grid (2, 32, KZ). BK=64 (4 chunk iterations per kz).
// ---------------------------------------------------------------------------
__global__ __launch_bounds__(256, 2) void mm_out_tc()
{
    __nv_bfloat16* sbuf = (__nv_bfloat16*)dyn_smem;

    const int m0 = blockIdx.y * 128, n0 = blockIdx.x * 128;
    const int kz = blockIdx.z;
    const int k0 = kz * (HD / KZ), k1 = k0 + (HD / KZ);
    const __nv_bfloat16* Ah = g_og_hi + (size_t)m0 * HD;
    const __nv_bfloat16* Al = g_og_lo + (size_t)m0 * HD;
    const __nv_bfloat16* Bh = g_wot_hi + (size_t)n0 * HD;
    const __nv_bfloat16* Bl = g_wot_lo + (size_t)n0 * HD;

    const int tid = threadIdx.x, lane = tid & 31, warp = tid >> 5;
    const int wm = warp >> 2, wn = warp & 3;
    const int lrow = lane & 15, lcolh = (lane >> 4) * 8;

    float acc[4][4][4] = {};

    for (int kc = k0; kc < k1; kc += 64) {
        #pragma unroll
        for (int i = 0; i < 4; i++) {
            int idx = tid + i * 256;
            int r = idx >> 3, g = (idx & 7) * 8;
            size_t src = (size_t)r * HD + kc + g;
            int dst = r * SPITCH + g;
            *(uint4*)&sbuf[dst] = *(const uint4*)&Ah[src];
            *(uint4*)&sbuf[RGN + dst] = *(const uint4*)&Al[src];
            *(uint4*)&sbuf[2 * RGN + dst] = *(const uint4*)&Bh[src];
            *(uint4*)&sbuf[3 * RGN + dst] = *(const uint4*)&Bl[src];
        }
        __syncthreads();
        mma_chunk64(sbuf, wm, wn, lrow, lcolh, acc);
        __syncthreads();
    }

    float* part = g_part + (size_t)kz * N_TOK * CDIM;
    const int l4 = lane >> 2, lq = lane & 3;
    #pragma unroll
    for (int mt = 0; mt < 4; mt++) {
        #pragma unroll
        for (int nt = 0; nt < 4; nt++) {
            #pragma unroll
            for (int rr = 0; rr < 2; rr++) {
                int m = m0 + wm * 64 + mt * 16 + l4 + rr * 8;
                int c = n0 + wn * 32 + nt * 8 + lq * 2;
                *(float2*)&part[(size_t)m * CDIM + c] =
                    make_float2(acc[mt][nt][rr * 2], acc[mt][nt][rr * 2 + 1]);
            }
        }
    }
}

__global__ __launch_bounds__(256) void reduce_out(float* __restrict__ out)
{
    int idx = (blockIdx.x * 256 + threadIdx.x) * 4;
    float4 a = *(const float4*)&g_part[idx];
    float4 b = *(const float4*)&g_part[N_TOK * CDIM + idx];
    float4 c = *(const float4*)&g_part[2 * N_TOK * CDIM + idx];
    float4 d = *(const float4*)&g_part[3 * N_TOK * CDIM + idx];
    float4 r = make_float4(a.x + b.x + c.x + d.x, a.y + b.y + c.y + d.y,
                           a.z + b.z + c.z + d.z, a.w + b.w + c.w + d.w);
    *(float4*)&out[idx] = r;
}

// ---------------------------------------------------------------------------
// tensor-core local attention — epilogue fused with gate multiply + bf16 split
// ---------------------------------------------------------------------------
#define QP 72
#define VP 264

__global__ __launch_bounds__(256) void attn_tc(const float* __restrict__ bias)
{
    __nv_bfloat16* Sb = (__nv_bfloat16*)dyn_smem;
    __nv_bfloat16* sQh = Sb;
    __nv_bfloat16* sQl = Sb + 4608;
    __nv_bfloat16* sKh = Sb + 9216;
    __nv_bfloat16* sKl = Sb + 27648;
    __nv_bfloat16* sVh = Sb + 9216;
    __nv_bfloat16* sVl = Sb + 26112;
    float* sO = (float*)dyn_smem;
    float* pm = (float*)(dyn_smem + 92160);
    float* ps = (float*)(dyn_smem + 92672);

    const int h = blockIdx.x, t = blockIdx.y;
    const int tid = threadIdx.x, lane = tid & 31, warp = tid >> 5;
    const int wm = warp & 3, ch = warp >> 2;
    const int kbase = t * NQ - PADL;
    const int lrow = lane & 15, lcolh = (lane >> 4) * 8;
    const int l4 = lane >> 2, lq = lane & 3;

    {
        const __nv_bfloat16* qh = g_qh + ((size_t)h * N_TOK + t * NQ) * DHEAD;
        const __nv_bfloat16* ql = g_ql + ((size_t)h * N_TOK + t * NQ) * DHEAD;
        #pragma unroll
        for (int i = 0; i < 2; i++) {
            int idx = tid + i * 256;
            int r = idx >> 3, g = idx & 7;
            *(uint4*)&sQh[r * QP + g * 8] = *(const uint4*)&qh[idx * 8];
            *(uint4*)&sQl[r * QP + g * 8] = *(const uint4*)&ql[idx * 8];
        }
        #pragma unroll
        for (int i = 0; i < 8; i++) {
            int idx = tid + i * 256;
            int r = idx >> 3, g = idx & 7;
            int gk = kbase + r;
            uint4 vh = {0, 0, 0, 0}, vl = {0, 0, 0, 0};
            if (gk >= 0 && gk < N_TOK) {
                size_t src = ((size_t)h * N_TOK + gk) * DHEAD + g * 8;
                vh = *(const uint4*)&g_kh[src];
                vl = *(const uint4*)&g_kl[src];
            }
            *(uint4*)&sKh[r * QP + g * 8] = vh;
            *(uint4*)&sKl[r * QP + g * 8] = vl;
        }
    }
    __syncthreads();

    uint32_t ah[4][4], al[4][4];
    #pragma unroll
    for (int kc = 0; kc < 4; kc++) {
        int ro = (wm * 16 + lrow) * QP + kc * 16 + lcolh;
        ldm_x4(smem_u32(&sQh[ro]), ah[kc]);
        ldm_x4(smem_u32(&sQl[ro]), al[kc]);
    }
    float acc[16][4];
    #pragma unroll
    for (int i = 0; i < 16; i++) { acc[i][0] = 0.f; acc[i][1] = 0.f; acc[i][2] = 0.f; acc[i][3] = 0.f; }
    #pragma unroll
    for (int nt = 0; nt < 8; nt++) {
        #pragma unroll
        for (int kc = 0; kc < 4; kc++) {
            uint32_t bh[4], bl[4];
            int ro = (ch * 128 + nt * 16 + lrow) * QP + kc * 16 + lcolh;
            ldm_x4(smem_u32(&sKh[ro]), bh);
            ldm_x4(smem_u32(&sKl[ro]), bl);
            mma16816(acc[2 * nt],     ah[kc], bh[0], bh[2]);
            mma16816(acc[2 * nt],     al[kc], bh[0], bh[2]);
            mma16816(acc[2 * nt],     ah[kc], bl[0], bl[2]);
            mma16816(acc[2 * nt + 1], ah[kc], bh[1], bh[3]);
            mma16816(acc[2 * nt + 1], al[kc], bh[1], bh[3]);
            mma16816(acc[2 * nt + 1], ah[kc], bl[1], bl[3]);
        }
    }

    {
        const int r0 = t * NQ + wm * 16 + l4;
        const int c0 = kbase + ch * 128 + lq * 2;
        #pragma unroll
        for (int nt = 0; nt < 16; nt++) {
            int gc = c0 + nt * 8;
            if (gc >= 0 && gc < N_TOK) {
                float2 b0 = *(const float2*)&bias[(size_t)r0 * N_TOK + gc];
                float2 b1 = *(const float2*)&bias[(size_t)(r0 + 8) * N_TOK + gc];
                acc[nt][0] += b0.x; acc[nt][1] += b0.y;
                acc[nt][2] += b1.x; acc[nt][3] += b1.y;
            }
        }
    }

    const int rloc = wm * 16 + l4;
    float mx0 = -1e30f, mx1 = -1e30f;
    #pragma unroll
    for (int nt = 0; nt < 16; nt++) {
        mx0 = fmaxf(mx0, fmaxf(acc[nt][0], acc[nt][1]));
        mx1 = fmaxf(mx1, fmaxf(acc[nt][2], acc[nt][3]));
    }
    mx0 = fmaxf(mx0, __shfl_xor_sync(0xffffffffu, mx0, 1));
    mx0 = fmaxf(mx0, __shfl_xor_sync(0xffffffffu, mx0, 2));
    mx1 = fmaxf(mx1, __shfl_xor_sync(0xffffffffu, mx1, 1));
    mx1 = fmaxf(mx1, __shfl_xor_sync(0xffffffffu, mx1, 2));
    if (lq == 0) { pm[ch * 64 + rloc] = mx0; pm[ch * 64 + rloc + 8] = mx1; }
    __syncthreads();

    float M0 = fmaxf(pm[rloc], pm[64 + rloc]);
    float M1 = fmaxf(pm[rloc + 8], pm[64 + rloc + 8]);
    float s0 = 0.f, s1 = 0.f;
    #pragma unroll
    for (int nt = 0; nt < 16; nt++) {
        acc[nt][0] = __expf(acc[nt][0] - M0); s0 += acc[nt][0];
        acc[nt][1] = __expf(acc[nt][1] - M0); s0 += acc[nt][1];
        acc[nt][2] = __expf(acc[nt][2] - M1); s1 += acc[nt][2];
        acc[nt][3] = __expf(acc[nt][3] - M1); s1 += acc[nt][3];
    }
    s0 += __shfl_xor_sync(0xffffffffu, s0, 1);
    s0 += __shfl_xor_sync(0xffffffffu, s0, 2);
    s1 += __shfl_xor_sync(0xffffffffu, s1, 1);
    s1 += __shfl_xor_sync(0xffffffffu, s1, 2);
    if (lq == 0) { ps[ch * 64 + rloc] = s0; ps[ch * 64 + rloc + 8] = s1; }

    #pragma unroll
    for (int i = 0; i < 8; i++) {
        int idx = tid + i * 256;
        int d = idx >> 5, g = idx & 31;
        int gk0 = kbase + g * 8;
        uint4 vh = {0, 0, 0, 0}, vl = {0, 0, 0, 0};
        if (gk0 >= 0 && gk0 < N_TOK) {
            size_t src = ((size_t)h * DHEAD + d) * N_TOK + gk0;
            vh = *(const uint4*)&g_vth[src];
            vl = *(const uint4*)&g_vtl[src];
        }
        *(uint4*)&sVh[d * VP + g * 8] = vh;
        *(uint4*)&sVl[d * VP + g * 8] = vl;
    }
    __syncthreads();

    float inv0 = 1.f / (ps[rloc] + ps[64 + rloc]);
    float inv1 = 1.f / (ps[rloc + 8] + ps[64 + rloc + 8]);
    #pragma unroll
    for (int nt = 0; nt < 16; nt++) {
        acc[nt][0] *= inv0; acc[nt][1] *= inv0;
        acc[nt][2] *= inv1; acc[nt][3] *= inv1;
    }

    float oacc[8][4];
    #pragma unroll
    for (int i = 0; i < 8; i++) { oacc[i][0] = 0.f; oacc[i][1] = 0.f; oacc[i][2] = 0.f; oacc[i][3] = 0.f; }
    #pragma unroll
    for (int kc = 0; kc < 8; kc++) {
        uint32_t awh[4], awl[4];
        #pragma unroll
        for (int f = 0; f < 4; f++) {
            int nt = 2 * kc + (f >> 1);
            int j = (f & 1) * 2;
            float x0 = acc[nt][j], x1 = acc[nt][j + 1];
            __nv_bfloat16 b0 = __float2bfloat16(x0), b1 = __float2bfloat16(x1);
            __nv_bfloat162 ph; ph.x = b0; ph.y = b1;
            awh[f] = *(uint32_t*)&ph;
            awl[f] = pack_bf16x2(x0 - __bfloat162float(b0), x1 - __bfloat162float(b1));
        }
        #pragma unroll
        for (int dg = 0; dg < 4; dg++) {
            uint32_t bh[4], bl[4];
            int ro = (dg * 16 + lrow) * VP + ch * 128 + kc * 16 + lcolh;
            ldm_x4(smem_u32(&sVh[ro]), bh);
            ldm_x4(smem_u32(&sVl[ro]), bl);
            mma16816(oacc[2 * dg],     awh, bh[0], bh[2]);
            mma16816(oacc[2 * dg],     awl, bh[0], bh[2]);
            mma16816(oacc[2 * dg],     awh, bl[0], bl[2]);
            mma16816(oacc[2 * dg + 1], awh, bh[1], bh[3]);
            mma16816(oacc[2 * dg + 1], awl, bh[1], bh[3]);
            mma16816(oacc[2 * dg + 1], awh, bl[1], bl[3]);
        }
    }

    // ---- combine halves, multiply by gate, split to bf16 hi/lo, store ----
    __syncthreads();
    if (ch == 1) {
        #pragma unroll
        for (int nt = 0; nt < 8; nt++) {
            int c = nt * 8 + lq * 2;
            sO[(wm * 16 + l4) * 66 + c] = oacc[nt][0];
            sO[(wm * 16 + l4) * 66 + c + 1] = oacc[nt][1];
            sO[(wm * 16 + l4 + 8) * 66 + c] = oacc[nt][2];
            sO[(wm * 16 + l4 + 8) * 66 + c + 1] = oacc[nt][3];
        }
    }
    __syncthreads();
    if (ch == 0) {
        #pragma unroll
        for (int nt = 0; nt < 8; nt++) {
            int r = wm * 16 + l4, c = nt * 8 + lq * 2;
            #pragma unroll
            for (int half = 0; half < 2; half++) {
                int rr = r + half * 8;
                float v0 = oacc[nt][half * 2]     + sO[rr * 66 + c];
                float v1 = oacc[nt][half * 2 + 1] + sO[rr * 66 + c + 1];
                size_t gi = (size_t)(t * NQ + rr) * HD + h * DHEAD + c;
                float2 gt = *(const float2*)&g_gate[gi];
                __nv_bfloat162 ph, pl;
                split2(v0 * gt.x, v1 * gt.y, &ph, &pl);
                *(__nv_bfloat162*)&g_og_hi[gi] = ph;
                *(__nv_bfloat162*)&g_og_lo[gi] = pl;
            }
        }
    }
}

// ---------------------------------------------------------------------------
extern "C" void kernel_launch(void* const* d_in, const int* in_sizes, int n_in,
                              void* d_out, int out_size)
{
    const float* qx   = (const float*)d_in[0];
    const float* kvx  = (const float*)d_in[1];
    const float* bias = (const float*)d_in[2];
    const float* Wq   = (const float*)d_in[3];
    const float* Wk   = (const float*)d_in[4];
    const float* Wv   = (const float*)d_in[5];
    const float* Wg   = (const float*)d_in[6];
    const float* Wo   = (const float*)d_in[7];
    float* out = (float*)d_out;

    static int configured = 0;
    if (!configured) {
        cudaFuncSetAttribute(attn_tc, cudaFuncAttributeMaxDynamicSharedMemorySize, 93184);
        cudaFuncSetAttribute(mm_proj_tc, cudaFuncAttributeMaxDynamicSharedMemorySize, SMEM_GEMM);
        cudaFuncSetAttribute(mm_out_tc, cudaFuncAttributeMaxDynamicSharedMemorySize, SMEM_GEMM);
        configured = 1;
    }

    conv_w<<<dim3(32, 32, 5), 256>>>(Wq, Wk, Wv, Wg, Wo);

    mm_proj_tc<<<dim3(HD / 128, N_TOK / 128, 4), 256, SMEM_GEMM>>>(qx, kvx);

    attn_tc<<<dim3(HEADS, NTRUNK), 256, 93184>>>(bias);

    mm_out_tc<<<dim3(CDIM / 128, N_TOK / 128, KZ), 256, SMEM_GEMM>>>();
    reduce_out<<<N_TOK * CDIM / 1024, 256>>>(out);
}

// round 12
// speedup vs baseline: 1.7143x; 1.0178x over previous
#include <cuda_runtime.h>
#include <cuda_bf16.h>
#include <math.h>
#include <stdint.h>

#define N_TOK 4096
#define CDIM 256
#define HEADS 16
#define DHEAD 64
#define HD 1024
#define NQ 64
#define NKEY 256
#define NTRUNK 64
#define PADL 96
#define KZ 4

extern __shared__ char dyn_smem[];

// ---------------- scratch (device globals) ----------------
__device__ float g_gate[N_TOK * HD];
__device__ float g_part[KZ * N_TOK * CDIM];

__device__ __align__(16) __nv_bfloat16 g_aq_hi[N_TOK * CDIM];
__device__ __align__(16) __nv_bfloat16 g_aq_lo[N_TOK * CDIM];
__device__ __align__(16) __nv_bfloat16 g_akv_hi[N_TOK * CDIM];
__device__ __align__(16) __nv_bfloat16 g_akv_lo[N_TOK * CDIM];
__device__ __align__(16) __nv_bfloat16 g_wt_hi[4 * HD * CDIM];   // [mat][n][k]
__device__ __align__(16) __nv_bfloat16 g_wt_lo[4 * HD * CDIM];
__device__ __align__(16) __nv_bfloat16 g_wot_hi[CDIM * HD];      // [n][k]
__device__ __align__(16) __nv_bfloat16 g_wot_lo[CDIM * HD];
__device__ __align__(16) __nv_bfloat16 g_og_hi[N_TOK * HD];
__device__ __align__(16) __nv_bfloat16 g_og_lo[N_TOK * HD];

// attention operands (bf16 hi/lo), q pre-scaled by 1/8
__device__ __align__(16) __nv_bfloat16 g_qh[HEADS * N_TOK * DHEAD];
__device__ __align__(16) __nv_bfloat16 g_ql[HEADS * N_TOK * DHEAD];
__device__ __align__(16) __nv_bfloat16 g_kh[HEADS * N_TOK * DHEAD];
__device__ __align__(16) __nv_bfloat16 g_kl[HEADS * N_TOK * DHEAD];
__device__ __align__(16) __nv_bfloat16 g_vth[HEADS * DHEAD * N_TOK]; // [h][d][n]
__device__ __align__(16) __nv_bfloat16 g_vtl[HEADS * DHEAD * N_TOK];

// ---------------- helpers ----------------
__device__ __forceinline__ uint32_t smem_u32(const void* p) {
    uint32_t a;
    asm("{ .reg .u64 t; cvta.to.shared.u64 t, %1; cvt.u32.u64 %0, t; }" : "=r"(a) : "l"(p));
    return a;
}

__device__ __forceinline__ void ldm_x4(uint32_t addr, uint32_t* r) {
    asm volatile("ldmatrix.sync.aligned.m8n8.x4.shared.b16 {%0,%1,%2,%3}, [%4];"
                 : "=r"(r[0]), "=r"(r[1]), "=r"(r[2]), "=r"(r[3]) : "r"(addr));
}

__device__ __forceinline__ void mma16816(float* c, const uint32_t* a, uint32_t b0, uint32_t b1) {
    asm volatile(
        "mma.sync.aligned.m16n8k16.row.col.f32.bf16.bf16.f32 "
        "{%0,%1,%2,%3}, {%4,%5,%6,%7}, {%8,%9}, {%0,%1,%2,%3};"
        : "+f"(c[0]), "+f"(c[1]), "+f"(c[2]), "+f"(c[3])
        : "r"(a[0]), "r"(a[1]), "r"(a[2]), "r"(a[3]), "r"(b0), "r"(b1));
}

__device__ __forceinline__ uint32_t pack_bf16x2(float x0, float x1) {
    __nv_bfloat162 p;
    p.x = __float2bfloat16(x0);
    p.y = __float2bfloat16(x1);
    return *(uint32_t*)&p;
}

__device__ __forceinline__ void split2(float x0, float x1,
                                       __nv_bfloat162* hi, __nv_bfloat162* lo) {
    __nv_bfloat16 b0 = __float2bfloat16(x0), b1 = __float2bfloat16(x1);
    hi->x = b0; hi->y = b1;
    lo->x = __float2bfloat16(x0 - __bfloat162float(b0));
    lo->y = __float2bfloat16(x1 - __bfloat162float(b1));
}

__device__ __forceinline__ void cp16(uint32_t d, const void* s) {
    asm volatile("cp.async.cg.shared.global [%0], [%1], 16;" :: "r"(d), "l"(s));
}

// GEMM smem: BK=32, pitch 40 halfwords; 4 regions of 10240 B; 2 stages.
#define SPITCH 40
#define RGN (128 * SPITCH)
#define AHOFF 0
#define ALOFF 10240
#define BHOFF 20480
#define BLOFF 30720
#define STG_BYTES 40960
#define SMEM_GEMM (2 * STG_BYTES)

// compute on one 32-wide K chunk resident at sbuf
__device__ __forceinline__ void mma_chunk(
    const __nv_bfloat16* sbuf, int wm, int wn, int lrow, int lcolh, float acc[4][4][4])
{
    #pragma unroll
    for (int ks = 0; ks < 2; ks++) {
        uint32_t ah[4][4], al[4][4];
        #pragma unroll
        for (int mt = 0; mt < 4; mt++) {
            int ro = (wm * 64 + mt * 16 + lrow) * SPITCH + ks * 16 + lcolh;
            ldm_x4(smem_u32(&sbuf[ro]), ah[mt]);
            ldm_x4(smem_u32(&sbuf[RGN + ro]), al[mt]);
        }
        #pragma unroll
        for (int bt = 0; bt < 2; bt++) {
            uint32_t bh[4], bl[4];
            int ro = (wn * 32 + bt * 16 + lrow) * SPITCH + ks * 16 + lcolh;
            ldm_x4(smem_u32(&sbuf[2 * RGN + ro]), bh);
            ldm_x4(smem_u32(&sbuf[3 * RGN + ro]), bl);
            #pragma unroll
            for (int mt = 0; mt < 4; mt++) {
                mma16816(acc[mt][bt * 2],     ah[mt], bh[0], bh[2]);
                mma16816(acc[mt][bt * 2],     al[mt], bh[0], bh[2]);
                mma16816(acc[mt][bt * 2],     ah[mt], bl[0], bl[2]);
                mma16816(acc[mt][bt * 2 + 1], ah[mt], bh[1], bh[3]);
                mma16816(acc[mt][bt * 2 + 1], al[mt], bh[1], bh[3]);
                mma16816(acc[mt][bt * 2 + 1], ah[mt], bl[1], bl[3]);
            }
        }
    }
}

// cp.async 2-stage pipelined GEMM mainloop (all operands bf16, K-major)
__device__ __forceinline__ void gemm_pipe(
    const __nv_bfloat16* __restrict__ Ah, const __nv_bfloat16* __restrict__ Al,
    const __nv_bfloat16* __restrict__ Bh, const __nv_bfloat16* __restrict__ Bl,
    int K, int kstart, int nk, float acc[4][4][4])
{
    const int tid = threadIdx.x, lane = tid & 31, warp = tid >> 5;
    const int wm = warp >> 2, wn = warp & 3;
    const int lrow = lane & 15, lcolh = (lane >> 4) * 8;
    const uint32_t sbase = smem_u32(dyn_smem);

    const int r0 = tid >> 2, g0 = (tid & 3) * 8;
    const int r1 = (tid + 256) >> 2, g1 = ((tid + 256) & 3) * 8;
    const uint32_t ds0 = (uint32_t)(r0 * SPITCH + g0) * 2;
    const uint32_t ds1 = (uint32_t)(r1 * SPITCH + g1) * 2;

    // prologue: stage 0
    {
        int kb = kstart;
        size_t o0 = (size_t)r0 * K + kb + g0;
        size_t o1 = (size_t)r1 * K + kb + g1;
        uint32_t b = sbase;
        cp16(b + AHOFF + ds0, Ah + o0); cp16(b + AHOFF + ds1, Ah + o1);
        cp16(b + ALOFF + ds0, Al + o0); cp16(b + ALOFF + ds1, Al + o1);
        cp16(b + BHOFF + ds0, Bh + o0); cp16(b + BHOFF + ds1, Bh + o1);
        cp16(b + BLOFF + ds0, Bl + o0); cp16(b + BLOFF + ds1, Bl + o1);
        asm volatile("cp.async.commit_group;");
    }

    for (int i = 0; i < nk; i++) {
        if (i + 1 < nk) {
            int kb = kstart + (i + 1) * 32;
            size_t o0 = (size_t)r0 * K + kb + g0;
            size_t o1 = (size_t)r1 * K + kb + g1;
            uint32_t b = sbase + ((i + 1) & 1) * STG_BYTES;
            cp16(b + AHOFF + ds0, Ah + o0); cp16(b + AHOFF + ds1, Ah + o1);
            cp16(b + ALOFF + ds0, Al + o0); cp16(b + ALOFF + ds1, Al + o1);
            cp16(b + BHOFF + ds0, Bh + o0); cp16(b + BHOFF + ds1, Bh + o1);
            cp16(b + BLOFF + ds0, Bl + o0); cp16(b + BLOFF + ds1, Bl + o1);
            asm volatile("cp.async.commit_group;");
            asm volatile("cp.async.wait_group 1;");
        } else {
            asm volatile("cp.async.wait_group 0;");
        }
        __syncthreads();
        mma_chunk((const __nv_bfloat16*)(dyn_smem + (i & 1) * STG_BYTES),
                  wm, wn, lrow, lcolh, acc);
        __syncthreads();
    }
}

// ---------------------------------------------------------------------------
// conversions
// ---------------------------------------------------------------------------
__global__ __launch_bounds__(256) void conv_act(const float* __restrict__ qx,
                                                const float* __restrict__ kvx)
{
    int idx = blockIdx.x * 256 + threadIdx.x;
    const float* src = blockIdx.y ? kvx : qx;
    __nv_bfloat16* hi = blockIdx.y ? g_akv_hi : g_aq_hi;
    __nv_bfloat16* lo = blockIdx.y ? g_akv_lo : g_aq_lo;
    float x = src[idx];
    __nv_bfloat16 h = __float2bfloat16(x);
    hi[idx] = h;
    lo[idx] = __float2bfloat16(x - __bfloat162float(h));
}

__global__ __launch_bounds__(256) void conv_w(
    const float* __restrict__ Wq, const float* __restrict__ Wk,
    const float* __restrict__ Wv, const float* __restrict__ Wg,
    const float* __restrict__ Wo)
{
    int z = blockIdx.z;
    const float* in; int R, C; __nv_bfloat16 *oh, *ol;
    if (z < 4) {
        in = (z == 0) ? Wq : (z == 1) ? Wk : (z == 2) ? Wv : Wg;
        R = CDIM; C = HD; oh = g_wt_hi + (size_t)z * HD * CDIM; ol = g_wt_lo + (size_t)z * HD * CDIM;
    } else {
        in = Wo; R = HD; C = CDIM; oh = g_wot_hi; ol = g_wot_lo;
    }
    int c0 = blockIdx.x * 32, r0 = blockIdx.y * 32;
    if (c0 >= C || r0 >= R) return;
    __shared__ float t[32][33];
    int tx = threadIdx.x & 31, ty = threadIdx.x >> 5;
    for (int i = ty; i < 32; i += 8) t[i][tx] = in[(size_t)(r0 + i) * C + c0 + tx];
    __syncthreads();
    for (int i = ty; i < 32; i += 8) {
        float x = t[tx][i];
        __nv_bfloat16 h = __float2bfloat16(x);
        size_t o = (size_t)(c0 + i) * R + r0 + tx;
        oh[o] = h;
        ol[o] = __float2bfloat16(x - __bfloat162float(h));
    }
}

// ---------------------------------------------------------------------------
// projection GEMMs: grid (8, 32, 4). BK=32 pipelined.
// ---------------------------------------------------------------------------
#define TPT 136

__global__ __launch_bounds__(256, 2) void mm_proj_tc()
{
    const int mat = blockIdx.z;
    const int m0 = blockIdx.y * 128, n0 = blockIdx.x * 128;
    const __nv_bfloat16* Ah = ((mat == 1 || mat == 2) ? g_akv_hi : g_aq_hi) + (size_t)m0 * CDIM;
    const __nv_bfloat16* Al = ((mat == 1 || mat == 2) ? g_akv_lo : g_aq_lo) + (size_t)m0 * CDIM;
    const __nv_bfloat16* Bh = g_wt_hi + (size_t)mat * HD * CDIM + (size_t)n0 * CDIM;
    const __nv_bfloat16* Bl = g_wt_lo + (size_t)mat * HD * CDIM + (size_t)n0 * CDIM;

    float acc[4][4][4] = {};
    gemm_pipe(Ah, Al, Bh, Bl, CDIM, 0, CDIM / 32, acc);

    const int tid = threadIdx.x, lane = tid & 31, warp = tid >> 5;
    const int wm = warp >> 2, wn = warp & 3;
    const int l4 = lane >> 2, lq = lane & 3;

    if (mat == 2) {
        __nv_bfloat16* sT = (__nv_bfloat16*)dyn_smem;
        #pragma unroll
        for (int pass = 0; pass < 2; pass++) {
            #pragma unroll
            for (int mt = 0; mt < 4; mt++) {
                #pragma unroll
                for (int nt = 0; nt < 4; nt++) {
                    #pragma unroll
                    for (int rr = 0; rr < 2; rr++) {
                        int ml = wm * 64 + mt * 16 + l4 + rr * 8;
                        int cl = wn * 32 + nt * 8 + lq * 2;
                        float v0 = acc[mt][nt][rr * 2], v1 = acc[mt][nt][rr * 2 + 1];
                        __nv_bfloat16 b0 = __float2bfloat16(v0), b1 = __float2bfloat16(v1);
                        if (pass == 0) {
                            sT[cl * TPT + ml] = b0;
                            sT[(cl + 1) * TPT + ml] = b1;
                        } else {
                            sT[cl * TPT + ml] = __float2bfloat16(v0 - __bfloat162float(b0));
                            sT[(cl + 1) * TPT + ml] = __float2bfloat16(v1 - __bfloat162float(b1));
                        }
                    }
                }
            }
            __syncthreads();
            {
                int cl = tid >> 1, half = tid & 1;
                int hh = (n0 + cl) >> 6, d = (n0 + cl) & 63;
                __nv_bfloat16* dst = (pass == 0 ? g_vth : g_vtl)
                                   + ((size_t)hh * DHEAD + d) * N_TOK + m0 + half * 64;
                const __nv_bfloat16* srcr = &sT[cl * TPT + half * 64];
                #pragma unroll
                for (int j = 0; j < 8; j++)
                    *(uint4*)&dst[j * 8] = *(const uint4*)&srcr[j * 8];
            }
            __syncthreads();
        }
        return;
    }

    #pragma unroll
    for (int mt = 0; mt < 4; mt++) {
        #pragma unroll
        for (int nt = 0; nt < 4; nt++) {
            #pragma unroll
            for (int rr = 0; rr < 2; rr++) {
                int m = m0 + wm * 64 + mt * 16 + l4 + rr * 8;
                int c = n0 + wn * 32 + nt * 8 + lq * 2;
                float v0 = acc[mt][nt][rr * 2], v1 = acc[mt][nt][rr * 2 + 1];
                int hh = c >> 6, d = c & 63;
                if (mat == 0) {
                    __nv_bfloat162 ph, pl;
                    split2(v0 * 0.125f, v1 * 0.125f, &ph, &pl);
                    size_t o = ((size_t)hh * N_TOK + m) * DHEAD + d;
                    *(__nv_bfloat162*)&g_qh[o] = ph;
                    *(__nv_bfloat162*)&g_ql[o] = pl;
                } else if (mat == 1) {
                    __nv_bfloat162 ph, pl;
                    split2(v0, v1, &ph, &pl);
                    size_t o = ((size_t)hh * N_TOK + m) * DHEAD + d;
                    *(__nv_bfloat162*)&g_kh[o] = ph;
                    *(__nv_bfloat162*)&g_kl[o] = pl;
                } else {
                    float2 v = make_float2(1.f / (1.f + expf(-v0)), 1.f / (1.f + expf(-v1)));
                    *(float2*)&g_gate[(size_t)m * HD + c] = v;
                }
            }
        }
    }
}

// ---------------------------------------------------------------------------
// output GEMM, split-K pipelined: grid (2, 32, KZ)
// ---------------------------------------------------------------------------
__global__ __launch_bounds__(256, 2) void mm_out_tc()
{
    const int m0 = blockIdx.y * 128, n0 = blockIdx.x * 128;
    const int kz = blockIdx.z;

    float acc[4][4][4] = {};
    gemm_pipe(g_og_hi + (size_t)m0 * HD, g_og_lo + (size_t)m0 * HD,
              g_wot_hi + (size_t)n0 * HD, g_wot_lo + (size_t)n0 * HD,
              HD, kz * (HD / KZ), (HD / KZ) / 32, acc);

    float* part = g_part + (size_t)kz * N_TOK * CDIM;
    const int lane = threadIdx.x & 31, warp = threadIdx.x >> 5;
    const int wm = warp >> 2, wn = warp & 3;
    const int l4 = lane >> 2, lq = lane & 3;
    #pragma unroll
    for (int mt = 0; mt < 4; mt++) {
        #pragma unroll
        for (int nt = 0; nt < 4; nt++) {
            #pragma unroll
            for (int rr = 0; rr < 2; rr++) {
                int m = m0 + wm * 64 + mt * 16 + l4 + rr * 8;
                int c = n0 + wn * 32 + nt * 8 + lq * 2;
                *(float2*)&part[(size_t)m * CDIM + c] =
                    make_float2(acc[mt][nt][rr * 2], acc[mt][nt][rr * 2 + 1]);
            }
        }
    }
}

__global__ __launch_bounds__(256) void reduce_out(float* __restrict__ out)
{
    int idx = (blockIdx.x * 256 + threadIdx.x) * 4;
    float4 a = *(const float4*)&g_part[idx];
    float4 b = *(const float4*)&g_part[N_TOK * CDIM + idx];
    float4 c = *(const float4*)&g_part[2 * N_TOK * CDIM + idx];
    float4 d = *(const float4*)&g_part[3 * N_TOK * CDIM + idx];
    float4 r = make_float4(a.x + b.x + c.x + d.x, a.y + b.y + c.y + d.y,
                           a.z + b.z + c.z + d.z, a.w + b.w + c.w + d.w);
    *(float4*)&out[idx] = r;
}

// ---------------------------------------------------------------------------
// tensor-core local attention — bias pre-loaded into accumulators,
// V load overlapped with softmax, gated bf16 epilogue.
// ---------------------------------------------------------------------------
#define QP 72
#define VP 264

__global__ __launch_bounds__(256) void attn_tc(const float* __restrict__ bias)
{
    __nv_bfloat16* Sb = (__nv_bfloat16*)dyn_smem;
    __nv_bfloat16* sQh = Sb;
    __nv_bfloat16* sQl = Sb + 4608;
    __nv_bfloat16* sKh = Sb + 9216;
    __nv_bfloat16* sKl = Sb + 27648;
    __nv_bfloat16* sVh = Sb + 9216;
    __nv_bfloat16* sVl = Sb + 26112;
    float* sO = (float*)dyn_smem;
    float* pm = (float*)(dyn_smem + 92160);
    float* ps = (float*)(dyn_smem + 92672);

    const int h = blockIdx.x, t = blockIdx.y;
    const int tid = threadIdx.x, lane = tid & 31, warp = tid >> 5;
    const int wm = warp & 3, ch = warp >> 2;
    const int kbase = t * NQ - PADL;
    const int lrow = lane & 15, lcolh = (lane >> 4) * 8;
    const int l4 = lane >> 2, lq = lane & 3;

    {
        const __nv_bfloat16* qh = g_qh + ((size_t)h * N_TOK + t * NQ) * DHEAD;
        const __nv_bfloat16* ql = g_ql + ((size_t)h * N_TOK + t * NQ) * DHEAD;
        #pragma unroll
        for (int i = 0; i < 2; i++) {
            int idx = tid + i * 256;
            int r = idx >> 3, g = idx & 7;
            *(uint4*)&sQh[r * QP + g * 8] = *(const uint4*)&qh[idx * 8];
            *(uint4*)&sQl[r * QP + g * 8] = *(const uint4*)&ql[idx * 8];
        }
        #pragma unroll
        for (int i = 0; i < 8; i++) {
            int idx = tid + i * 256;
            int r = idx >> 3, g = idx & 7;
            int gk = kbase + r;
            uint4 vh = {0, 0, 0, 0}, vl = {0, 0, 0, 0};
            if (gk >= 0 && gk < N_TOK) {
                size_t src = ((size_t)h * N_TOK + gk) * DHEAD + g * 8;
                vh = *(const uint4*)&g_kh[src];
                vl = *(const uint4*)&g_kl[src];
            }
            *(uint4*)&sKh[r * QP + g * 8] = vh;
            *(uint4*)&sKl[r * QP + g * 8] = vl;
        }
    }

    // init accumulators with bias (loads overlap the smem fill + S mma)
    float acc[16][4];
    {
        const int r0 = t * NQ + wm * 16 + l4;
        const int c0 = kbase + ch * 128 + lq * 2;
        #pragma unroll
        for (int nt = 0; nt < 16; nt++) {
            int gc = c0 + nt * 8;
            if (gc >= 0 && gc < N_TOK) {
                float2 b0 = *(const float2*)&bias[(size_t)r0 * N_TOK + gc];
                float2 b1 = *(const float2*)&bias[(size_t)(r0 + 8) * N_TOK + gc];
                acc[nt][0] = b0.x; acc[nt][1] = b0.y;
                acc[nt][2] = b1.x; acc[nt][3] = b1.y;
            } else {
                acc[nt][0] = 0.f; acc[nt][1] = 0.f; acc[nt][2] = 0.f; acc[nt][3] = 0.f;
            }
        }
    }
    __syncthreads();

    uint32_t ah[4][4], al[4][4];
    #pragma unroll
    for (int kc = 0; kc < 4; kc++) {
        int ro = (wm * 16 + lrow) * QP + kc * 16 + lcolh;
        ldm_x4(smem_u32(&sQh[ro]), ah[kc]);
        ldm_x4(smem_u32(&sQl[ro]), al[kc]);
    }
    #pragma unroll
    for (int nt = 0; nt < 8; nt++) {
        #pragma unroll
        for (int kc = 0; kc < 4; kc++) {
            uint32_t bh[4], bl[4];
            int ro = (ch * 128 + nt * 16 + lrow) * QP + kc * 16 + lcolh;
            ldm_x4(smem_u32(&sKh[ro]), bh);
            ldm_x4(smem_u32(&sKl[ro]), bl);
            mma16816(acc[2 * nt],     ah[kc], bh[0], bh[2]);
            mma16816(acc[2 * nt],     al[kc], bh[0], bh[2]);
            mma16816(acc[2 * nt],     ah[kc], bl[0], bl[2]);
            mma16816(acc[2 * nt + 1], ah[kc], bh[1], bh[3]);
            mma16816(acc[2 * nt + 1], al[kc], bh[1], bh[3]);
            mma16816(acc[2 * nt + 1], ah[kc], bl[1], bl[3]);
        }
    }

    const int rloc = wm * 16 + l4;
    float mx0 = -1e30f, mx1 = -1e30f;
    #pragma unroll
    for (int nt = 0; nt < 16; nt++) {
        mx0 = fmaxf(mx0, fmaxf(acc[nt][0], acc[nt][1]));
        mx1 = fmaxf(mx1, fmaxf(acc[nt][2], acc[nt][3]));
    }
    mx0 = fmaxf(mx0, __shfl_xor_sync(0xffffffffu, mx0, 1));
    mx0 = fmaxf(mx0, __shfl_xor_sync(0xffffffffu, mx0, 2));
    mx1 = fmaxf(mx1, __shfl_xor_sync(0xffffffffu, mx1, 1));
    mx1 = fmaxf(mx1, __shfl_xor_sync(0xffffffffu, mx1, 2));
    if (lq == 0) { pm[ch * 64 + rloc] = mx0; pm[ch * 64 + rloc + 8] = mx1; }
    __syncthreads();   // all sK reads retired; pm visible

    // V load first (overlaps the exp/sum math below)
    #pragma unroll
    for (int i = 0; i < 8; i++) {
        int idx = tid + i * 256;
        int d = idx >> 5, g = idx & 31;
        int gk0 = kbase + g * 8;
        uint4 vh = {0, 0, 0, 0}, vl = {0, 0, 0, 0};
        if (gk0 >= 0 && gk0 < N_TOK) {
            size_t src = ((size_t)h * DHEAD + d) * N_TOK + gk0;
            vh = *(const uint4*)&g_vth[src];
            vl = *(const uint4*)&g_vtl[src];
        }
        *(uint4*)&sVh[d * VP + g * 8] = vh;
        *(uint4*)&sVl[d * VP + g * 8] = vl;
    }

    float M0 = fmaxf(pm[rloc], pm[64 + rloc]);
    float M1 = fmaxf(pm[rloc + 8], pm[64 + rloc + 8]);
    float s0 = 0.f, s1 = 0.f;
    #pragma unroll
    for (int nt = 0; nt < 16; nt++) {
        acc[nt][0] = __expf(acc[nt][0] - M0); s0 += acc[nt][0];
        acc[nt][1] = __expf(acc[nt][1] - M0); s0 += acc[nt][1];
        acc[nt][2] = __expf(acc[nt][2] - M1); s1 += acc[nt][2];
        acc[nt][3] = __expf(acc[nt][3] - M1); s1 += acc[nt][3];
    }
    s0 += __shfl_xor_sync(0xffffffffu, s0, 1);
    s0 += __shfl_xor_sync(0xffffffffu, s0, 2);
    s1 += __shfl_xor_sync(0xffffffffu, s1, 1);
    s1 += __shfl_xor_sync(0xffffffffu, s1, 2);
    if (lq == 0) { ps[ch * 64 + rloc] = s0; ps[ch * 64 + rloc + 8] = s1; }
    __syncthreads();   // ps visible + V resident

    float inv0 = 1.f / (ps[rloc] + ps[64 + rloc]);
    float inv1 = 1.f / (ps[rloc + 8] + ps[64 + rloc + 8]);
    #pragma unroll
    for (int nt = 0; nt < 16; nt++) {
        acc[nt][0] *= inv0; acc[nt][1] *= inv0;
        acc[nt][2] *= inv1; acc[nt][3] *= inv1;
    }

    float oacc[8][4];
    #pragma unroll
    for (int i = 0; i < 8; i++) { oacc[i][0] = 0.f; oacc[i][1] = 0.f; oacc[i][2] = 0.f; oacc[i][3] = 0.f; }
    #pragma unroll
    for (int kc = 0; kc < 8; kc++) {
        uint32_t awh[4], awl[4];
        #pragma unroll
        for (int f = 0; f < 4; f++) {
            int nt = 2 * kc + (f >> 1);
            int j = (f & 1) * 2;
            float x0 = acc[nt][j], x1 = acc[nt][j + 1];
            __nv_bfloat16 b0 = __float2bfloat16(x0), b1 = __float2bfloat16(x1);
            __nv_bfloat162 ph; ph.x = b0; ph.y = b1;
            awh[f] = *(uint32_t*)&ph;
            awl[f] = pack_bf16x2(x0 - __bfloat162float(b0), x1 - __bfloat162float(b1));
        }
        #pragma unroll
        for (int dg = 0; dg < 4; dg++) {
            uint32_t bh[4], bl[4];
            int ro = (dg * 16 + lrow) * VP + ch * 128 + kc * 16 + lcolh;
            ldm_x4(smem_u32(&sVh[ro]), bh);
            ldm_x4(smem_u32(&sVl[ro]), bl);
            mma16816(oacc[2 * dg],     awh, bh[0], bh[2]);
            mma16816(oacc[2 * dg],     awl, bh[0], bh[2]);
            mma16816(oacc[2 * dg],     awh, bl[0], bl[2]);
            mma16816(oacc[2 * dg + 1], awh, bh[1], bh[3]);
            mma16816(oacc[2 * dg + 1], awl, bh[1], bh[3]);
            mma16816(oacc[2 * dg + 1], awh, bl[1], bl[3]);
        }
    }

    __syncthreads();
    if (ch == 1) {
        #pragma unroll
        for (int nt = 0; nt < 8; nt++) {
            int c = nt * 8 + lq * 2;
            sO[(wm * 16 + l4) * 66 + c] = oacc[nt][0];
            sO[(wm * 16 + l4) * 66 + c + 1] = oacc[nt][1];
            sO[(wm * 16 + l4 + 8) * 66 + c] = oacc[nt][2];
            sO[(wm * 16 + l4 + 8) * 66 + c + 1] = oacc[nt][3];
        }
    }
    __syncthreads();
    if (ch == 0) {
        #pragma unroll
        for (int nt = 0; nt < 8; nt++) {
            int r = wm * 16 + l4, c = nt * 8 + lq * 2;
            #pragma unroll
            for (int half = 0; half < 2; half++) {
                int rr = r + half * 8;
                float v0 = oacc[nt][half * 2]     + sO[rr * 66 + c];
                float v1 = oacc[nt][half * 2 + 1] + sO[rr * 66 + c + 1];
                size_t gi = (size_t)(t * NQ + rr) * HD + h * DHEAD + c;
                float2 gt = *(const float2*)&g_gate[gi];
                __nv_bfloat162 ph, pl;
                split2(v0 * gt.x, v1 * gt.y, &ph, &pl);
                *(__nv_bfloat162*)&g_og_hi[gi] = ph;
                *(__nv_bfloat162*)&g_og_lo[gi] = pl;
            }
        }
    }
}

// ---------------------------------------------------------------------------
extern "C" void kernel_launch(void* const* d_in, const int* in_sizes, int n_in,
                              void* d_out, int out_size)
{
    const float* qx   = (const float*)d_in[0];
    const float* kvx  = (const float*)d_in[1];
    const float* bias = (const float*)d_in[2];
    const float* Wq   = (const float*)d_in[3];
    const float* Wk   = (const float*)d_in[4];
    const float* Wv   = (const float*)d_in[5];
    const float* Wg   = (const float*)d_in[6];
    const float* Wo   = (const float*)d_in[7];
    float* out = (float*)d_out;

    static int configured = 0;
    if (!configured) {
        cudaFuncSetAttribute(attn_tc, cudaFuncAttributeMaxDynamicSharedMemorySize, 93184);
        cudaFuncSetAttribute(mm_proj_tc, cudaFuncAttributeMaxDynamicSharedMemorySize, SMEM_GEMM);
        cudaFuncSetAttribute(mm_out_tc, cudaFuncAttributeMaxDynamicSharedMemorySize, SMEM_GEMM);
        configured = 1;
    }

    conv_act<<<dim3(N_TOK * CDIM / 256, 2), 256>>>(qx, kvx);
    conv_w<<<dim3(32, 32, 5), 256>>>(Wq, Wk, Wv, Wg, Wo);

    mm_proj_tc<<<dim3(HD / 128, N_TOK / 128, 4), 256, SMEM_GEMM>>>();

    attn_tc<<<dim3(HEADS, NTRUNK), 256, 93184>>>(bias);

    mm_out_tc<<<dim3(CDIM / 128, N_TOK / 128, KZ), 256, SMEM_GEMM>>>();
    reduce_out<<<N_TOK * CDIM / 1024, 256>>>(out);
}